// round 1
// baseline (speedup 1.0000x reference)
#include <cuda_runtime.h>
#include <cuda_bf16.h>
#include <math.h>

#define BATCH 2
#define SEQ 2048
#define DMODEL 2048
#define NH 32
#define NKV 8
#define HD 64
#define TOKENS (BATCH * SEQ) /* 4096 */

// Scratch (no cudaMalloc allowed): ~84MB of device globals.
__device__ float g_q[TOKENS * NH * HD];
__device__ float g_k[TOKENS * NKV * HD];
__device__ float g_v[TOKENS * NKV * HD];
__device__ float g_o[TOKENS * NH * HD];

// ---------------------------------------------------------------------------
// SGEMM: C[M,N] = A[M,K] @ B[K,N], all row-major fp32.
// 128x128 tile, BK=8, 256 threads, 8x8 per-thread microtile.
// Requires M%128==0, N%128==0, K%8==0 (true for all call sites).
// ---------------------------------------------------------------------------
__global__ void sgemm_kernel(const float* __restrict__ A,
                             const float* __restrict__ B,
                             float* __restrict__ C,
                             int M, int N, int K) {
    __shared__ float As[8][128];
    __shared__ float Bs[8][128];

    const int tid  = threadIdx.x;
    const int brow = blockIdx.y * 128;
    const int bcol = blockIdx.x * 128;
    const int tx   = tid & 15;
    const int ty   = tid >> 4;
    const int aRow = tid >> 1;
    const int aCol = (tid & 1) * 4;
    const int bRow = tid >> 5;
    const int bCol = (tid & 31) * 4;

    const float* Ap = A + (size_t)(brow + aRow) * K + aCol;
    const float* Bp = B + (size_t)bRow * N + bcol + bCol;

    float acc[8][8];
#pragma unroll
    for (int i = 0; i < 8; i++)
#pragma unroll
        for (int j = 0; j < 8; j++) acc[i][j] = 0.0f;

    for (int k0 = 0; k0 < K; k0 += 8) {
        float4 av = *(const float4*)Ap;
        float4 bv = *(const float4*)Bp;
        Ap += 8;
        Bp += (size_t)8 * N;

        __syncthreads();
        As[aCol + 0][aRow] = av.x;
        As[aCol + 1][aRow] = av.y;
        As[aCol + 2][aRow] = av.z;
        As[aCol + 3][aRow] = av.w;
        *(float4*)&Bs[bRow][bCol] = bv;
        __syncthreads();

#pragma unroll
        for (int kk = 0; kk < 8; kk++) {
            float ar[8], br[8];
            *(float4*)&ar[0] = *(const float4*)&As[kk][ty * 8];
            *(float4*)&ar[4] = *(const float4*)&As[kk][ty * 8 + 4];
            *(float4*)&br[0] = *(const float4*)&Bs[kk][tx * 8];
            *(float4*)&br[4] = *(const float4*)&Bs[kk][tx * 8 + 4];
#pragma unroll
            for (int i = 0; i < 8; i++)
#pragma unroll
                for (int j = 0; j < 8; j++) acc[i][j] += ar[i] * br[j];
        }
    }

#pragma unroll
    for (int i = 0; i < 8; i++) {
        float* crow = C + (size_t)(brow + ty * 8 + i) * N + bcol + tx * 8;
        *(float4*)crow       = make_float4(acc[i][0], acc[i][1], acc[i][2], acc[i][3]);
        *(float4*)(crow + 4) = make_float4(acc[i][4], acc[i][5], acc[i][6], acc[i][7]);
    }
}

// ---------------------------------------------------------------------------
// RoPE (in place on g_q / g_k). One thread per rotation pair.
//   out[i]    = x[i]   * cos[i]    - x[i+32] * sin[i]
//   out[i+32] = x[i+32]* cos[i+32] + x[i]    * sin[i+32]
// ---------------------------------------------------------------------------
__global__ void rope_kernel(float* __restrict__ q, float* __restrict__ k,
                            const float* __restrict__ cosp,
                            const float* __restrict__ sinp) {
    const int HALF = HD / 2;
    const int total_q = TOKENS * NH * HALF;
    const int total   = total_q + TOKENS * NKV * HALF;
    int idx = blockIdx.x * blockDim.x + threadIdx.x;
    if (idx >= total) return;

    float* ptr;
    int tok, i;
    if (idx < total_q) {
        i = idx % HALF;
        int t = idx / HALF;
        int head = t % NH;
        tok = t / NH;
        ptr = q + ((size_t)tok * NH + head) * HD;
    } else {
        int id2 = idx - total_q;
        i = id2 % HALF;
        int t = id2 / HALF;
        int head = t % NKV;
        tok = t / NKV;
        ptr = k + ((size_t)tok * NKV + head) * HD;
    }
    int pos = tok & (SEQ - 1);
    float c0 = cosp[pos * HD + i];
    float s0 = sinp[pos * HD + i];
    float c1 = cosp[pos * HD + HALF + i];
    float s1 = sinp[pos * HD + HALF + i];
    float a = ptr[i];
    float b = ptr[i + HALF];
    ptr[i]        = a * c0 - b * s0;
    ptr[i + HALF] = b * c1 + a * s1;
}

// ---------------------------------------------------------------------------
// Causal GQA flash attention, fp32.
// Grid: (qt=SEQ/64, h=NH, b=BATCH).  256 threads = 8 warps.
// Warp w owns query rows w*8..w*8+7 of the 64-row tile.
// Lane owns key/value columns (lane, lane+32).
// smem: Qs (plain) + Ks (XOR swizzled, aliased as P tile) + Vs (plain) = 48KB.
// ---------------------------------------------------------------------------
__global__ __launch_bounds__(256) void attn_kernel(
    const float* __restrict__ q, const float* __restrict__ k,
    const float* __restrict__ v, float* __restrict__ o) {
    __shared__ float Qs[64 * 64];
    __shared__ float Ks[64 * 64];  // swizzled K; reused (plain layout) as P tile
    __shared__ float Vs[64 * 64];

    const int qt   = blockIdx.x;
    const int h    = blockIdx.y;
    const int b    = blockIdx.z;
    const int kvh  = h >> 2;  // REP = 4 (repeat_interleave)
    const int tid  = threadIdx.x;
    const int w    = tid >> 5;
    const int lane = tid & 31;
    const int c0   = lane;
    const int c1   = lane + 32;

    const float scale = 0.125f;  // 1/sqrt(64)

    // Load Q tile, pre-scaled.
    const float* qbase = q + ((size_t)(b * SEQ + qt * 64) * NH + h) * HD;
    for (int idx = tid; idx < 64 * 64; idx += 256) {
        int r = idx >> 6, d = idx & 63;
        Qs[idx] = qbase[(size_t)r * (NH * HD) + d] * scale;
    }

    float O0[8], O1[8], m[8], l[8];
#pragma unroll
    for (int r = 0; r < 8; r++) {
        O0[r] = 0.0f; O1[r] = 0.0f; m[r] = -1e30f; l[r] = 0.0f;
    }

    for (int kt = 0; kt <= qt; kt++) {
        __syncthreads();  // prior iter done with Ks(P)/Vs; Qs store visible
        const float* kbase = k + ((size_t)(b * SEQ + kt * 64) * NKV + kvh) * HD;
        const float* vbase = v + ((size_t)(b * SEQ + kt * 64) * NKV + kvh) * HD;
        for (int idx = tid; idx < 64 * 64; idx += 256) {
            int r = idx >> 6, d = idx & 63;
            Ks[r * 64 + (d ^ r)] = kbase[(size_t)r * (NKV * HD) + d];
            Vs[idx]              = vbase[(size_t)r * (NKV * HD) + d];
        }
        __syncthreads();

        // S = Q @ K^T for this warp's 8 rows x this lane's 2 cols.
        float S0[8], S1[8];
#pragma unroll
        for (int r = 0; r < 8; r++) { S0[r] = 0.0f; S1[r] = 0.0f; }
        for (int d = 0; d < 64; d++) {
            float k0v = Ks[c0 * 64 + (d ^ c0)];
            float k1v = Ks[c1 * 64 + (d ^ c1)];
#pragma unroll
            for (int r = 0; r < 8; r++) {
                float qv = Qs[(w * 8 + r) * 64 + d];  // warp-broadcast
                S0[r] += qv * k0v;
                S1[r] += qv * k1v;
            }
        }

        // Online softmax (rows live entirely inside one warp).
#pragma unroll
        for (int r = 0; r < 8; r++) {
            int row = w * 8 + r;
            if (kt == qt) {
                if (c0 > row) S0[r] = -1e30f;
                if (c1 > row) S1[r] = -1e30f;
            }
            float mr = fmaxf(S0[r], S1[r]);
#pragma unroll
            for (int off = 16; off > 0; off >>= 1)
                mr = fmaxf(mr, __shfl_xor_sync(0xffffffffu, mr, off));
            float mn   = fmaxf(m[r], mr);
            float p0   = __expf(S0[r] - mn);
            float p1   = __expf(S1[r] - mn);
            float corr = __expf(m[r] - mn);
            float ls   = p0 + p1;
#pragma unroll
            for (int off = 16; off > 0; off >>= 1)
                ls += __shfl_xor_sync(0xffffffffu, ls, off);
            l[r]  = l[r] * corr + ls;
            O0[r] *= corr;
            O1[r] *= corr;
            m[r]  = mn;
            S0[r] = p0;  // reuse S regs as P
            S1[r] = p1;
        }

        __syncthreads();  // everyone done reading Ks before P overwrites it
        float* Ps = Ks;   // plain [row][col] layout
#pragma unroll
        for (int r = 0; r < 8; r++) {
            Ps[(w * 8 + r) * 64 + c0] = S0[r];
            Ps[(w * 8 + r) * 64 + c1] = S1[r];
        }
        __syncthreads();

        // O += P @ V
        for (int j = 0; j < 64; j++) {
            float v0 = Vs[j * 64 + c0];
            float v1 = Vs[j * 64 + c1];
#pragma unroll
            for (int r = 0; r < 8; r++) {
                float p = Ps[(w * 8 + r) * 64 + j];  // warp-broadcast
                O0[r] += p * v0;
                O1[r] += p * v1;
            }
        }
    }

    // Epilogue: normalize and store.
    float* obase = o + ((size_t)(b * SEQ + qt * 64) * NH + h) * HD;
#pragma unroll
    for (int r = 0; r < 8; r++) {
        float inv = 1.0f / l[r];
        obase[(size_t)(w * 8 + r) * (NH * HD) + c0] = O0[r] * inv;
        obase[(size_t)(w * 8 + r) * (NH * HD) + c1] = O1[r] * inv;
    }
}

// ---------------------------------------------------------------------------
extern "C" void kernel_launch(void* const* d_in, const int* in_sizes, int n_in,
                              void* d_out, int out_size) {
    const float* x    = (const float*)d_in[0];
    const float* cosp = (const float*)d_in[1];
    const float* sinp = (const float*)d_in[2];
    const float* wq   = (const float*)d_in[3];
    const float* wk   = (const float*)d_in[4];
    const float* wv   = (const float*)d_in[5];
    const float* wo   = (const float*)d_in[6];
    float* out        = (float*)d_out;

    float *pq, *pk, *pv, *po;
    cudaGetSymbolAddress((void**)&pq, g_q);
    cudaGetSymbolAddress((void**)&pk, g_k);
    cudaGetSymbolAddress((void**)&pv, g_v);
    cudaGetSymbolAddress((void**)&po, g_o);

    // Projections
    sgemm_kernel<<<dim3(DMODEL / 128, TOKENS / 128), 256>>>(
        x, wq, pq, TOKENS, NH * HD, DMODEL);
    sgemm_kernel<<<dim3((NKV * HD) / 128, TOKENS / 128), 256>>>(
        x, wk, pk, TOKENS, NKV * HD, DMODEL);
    sgemm_kernel<<<dim3((NKV * HD) / 128, TOKENS / 128), 256>>>(
        x, wv, pv, TOKENS, NKV * HD, DMODEL);

    // RoPE on q and k
    {
        int total = TOKENS * NH * (HD / 2) + TOKENS * NKV * (HD / 2);
        int blocks = (total + 255) / 256;
        rope_kernel<<<blocks, 256>>>(pq, pk, cosp, sinp);
    }

    // Attention
    attn_kernel<<<dim3(SEQ / 64, NH, BATCH), 256>>>(pq, pk, pv, po);

    // Output projection
    sgemm_kernel<<<dim3(DMODEL / 128, TOKENS / 128), 256>>>(
        po, wo, out, TOKENS, DMODEL, DMODEL);
}

// round 2
// speedup vs baseline: 1.5971x; 1.5971x over previous
#include <cuda_runtime.h>
#include <cuda_bf16.h>
#include <math.h>

#define BATCH 2
#define SEQ 2048
#define DMODEL 2048
#define NH 32
#define NKV 8
#define HD 64
#define TOKENS (BATCH * SEQ) /* 4096 */
#define KP (3 * DMODEL)      /* 6144 expanded-K for bf16x3 */

// ---------------- scratch (device globals; no cudaMalloc allowed) ----------
__device__ float g_q[TOKENS * NH * HD];
__device__ float g_k[TOKENS * NKV * HD];
__device__ float g_v[TOKENS * NKV * HD];
__device__ float g_o[TOKENS * NH * HD];

__device__ __nv_bfloat16 g_xs[TOKENS * KP];        // split(x)   [M, 3K]
__device__ __nv_bfloat16 g_os[TOKENS * KP];        // split(o)   [M, 3K]
__device__ __nv_bfloat16 g_wqs[KP * DMODEL];       // split(wq)  [3K, N]
__device__ __nv_bfloat16 g_wks[KP * (NKV * HD)];
__device__ __nv_bfloat16 g_wvs[KP * (NKV * HD)];
__device__ __nv_bfloat16 g_wos[KP * DMODEL];

// ---------------------------------------------------------------------------
// bf16x3 split kernels.
// A-side: in fp32 [M,K] -> out bf16 [M,3K] as [hi | lo | hi] along K.
// B-side: in fp32 [K,N] -> out bf16 [3K,N] as rows [hi ; hi ; lo].
// Pairing over K' gives Ah*Bh + Al*Bh + Ah*Bl.
// ---------------------------------------------------------------------------
__device__ __forceinline__ void split4(float4 v, unsigned& hi, unsigned& lo) {
    __nv_bfloat16 h0 = __float2bfloat16_rn(v.x);
    __nv_bfloat16 h1 = __float2bfloat16_rn(v.y);
    __nv_bfloat16 h2 = __float2bfloat16_rn(v.z);
    __nv_bfloat16 h3 = __float2bfloat16_rn(v.w);
    __nv_bfloat16 l0 = __float2bfloat16_rn(v.x - __bfloat162float(h0));
    __nv_bfloat16 l1 = __float2bfloat16_rn(v.y - __bfloat162float(h1));
    __nv_bfloat16 l2 = __float2bfloat16_rn(v.z - __bfloat162float(h2));
    __nv_bfloat16 l3 = __float2bfloat16_rn(v.w - __bfloat162float(h3));
    hi = 0; lo = 0; // packed below via memcpy-style
    unsigned short* hp = (unsigned short*)&hi;
    unsigned short* lp = (unsigned short*)&lo;
    hp[0] = *(unsigned short*)&h0; hp[1] = *(unsigned short*)&h1;
    lp[0] = *(unsigned short*)&l0; lp[1] = *(unsigned short*)&l1;
    // second pair returned via globals? no — do two calls instead
    (void)h2; (void)h3; (void)l2; (void)l3;
}

__global__ void split_A_kernel(const float* __restrict__ in,
                               __nv_bfloat16* __restrict__ out,
                               int M, int K) {
    int idx = blockIdx.x * blockDim.x + threadIdx.x;   // one per 4 elems
    int total = M * K / 4;
    if (idx >= total) return;
    int m = idx / (K / 4);
    int c = (idx % (K / 4)) * 4;
    float4 v = *(const float4*)(in + (size_t)m * K + c);
    __nv_bfloat16 h[4], l[4];
    float vv[4] = {v.x, v.y, v.z, v.w};
#pragma unroll
    for (int i = 0; i < 4; i++) {
        h[i] = __float2bfloat16_rn(vv[i]);
        l[i] = __float2bfloat16_rn(vv[i] - __bfloat162float(h[i]));
    }
    uint2 hp, lp;
    unsigned short* hs = (unsigned short*)&hp;
    unsigned short* ls = (unsigned short*)&lp;
#pragma unroll
    for (int i = 0; i < 4; i++) { hs[i] = *(unsigned short*)&h[i]; ls[i] = *(unsigned short*)&l[i]; }
    size_t base = (size_t)m * (3 * K);
    *(uint2*)(out + base + c)         = hp;
    *(uint2*)(out + base + K + c)     = lp;
    *(uint2*)(out + base + 2 * K + c) = hp;
}

__global__ void split_B_kernel(const float* __restrict__ in,
                               __nv_bfloat16* __restrict__ out,
                               int K, int N) {
    int idx = blockIdx.x * blockDim.x + threadIdx.x;
    int total = K * N / 4;
    if (idx >= total) return;
    int r = idx / (N / 4);
    int c = (idx % (N / 4)) * 4;
    float4 v = *(const float4*)(in + (size_t)r * N + c);
    __nv_bfloat16 h[4], l[4];
    float vv[4] = {v.x, v.y, v.z, v.w};
#pragma unroll
    for (int i = 0; i < 4; i++) {
        h[i] = __float2bfloat16_rn(vv[i]);
        l[i] = __float2bfloat16_rn(vv[i] - __bfloat162float(h[i]));
    }
    uint2 hp, lp;
    unsigned short* hs = (unsigned short*)&hp;
    unsigned short* ls = (unsigned short*)&lp;
#pragma unroll
    for (int i = 0; i < 4; i++) { hs[i] = *(unsigned short*)&h[i]; ls[i] = *(unsigned short*)&l[i]; }
    *(uint2*)(out + (size_t)r * N + c)           = hp;
    *(uint2*)(out + (size_t)(K + r) * N + c)     = hp;
    *(uint2*)(out + (size_t)(2 * K + r) * N + c) = lp;
}

// ---------------------------------------------------------------------------
// bf16 tensor-core GEMM: C[M,N] fp32 = A[M,Kp] bf16 @ B[Kp,N] bf16.
// 128x128 tile, BK=32, 256 threads (8 warps, 2x4), warp tile 64x32,
// mma.sync.m16n8k16, cp.async double buffering.
// Requires M%128==0, N%128==0, Kp%32==0.
// ---------------------------------------------------------------------------
#define APAD 40   /* A smem row stride in bf16 (32 + 8) */
#define BPAD 136  /* B smem row stride in bf16 (128 + 8) */

__device__ __forceinline__ void cp16(unsigned s, const void* g) {
    asm volatile("cp.async.cg.shared.global [%0], [%1], 16;\n" :: "r"(s), "l"(g));
}
__device__ __forceinline__ void cp_commit() {
    asm volatile("cp.async.commit_group;\n");
}
__device__ __forceinline__ void cp_wait1() {
    asm volatile("cp.async.wait_group 1;\n");
}

__global__ __launch_bounds__(256) void bgemm_kernel(
    const __nv_bfloat16* __restrict__ A,
    const __nv_bfloat16* __restrict__ B,
    float* __restrict__ C,
    int M, int N, int Kp) {
    __shared__ __nv_bfloat16 As[2][128 * APAD];
    __shared__ __nv_bfloat16 Bs[2][32 * BPAD];

    const int tid  = threadIdx.x;
    const int lane = tid & 31;
    const int wid  = tid >> 5;
    const int wm   = wid >> 2;       // 0..1  -> 64 rows
    const int wn   = wid & 3;        // 0..3  -> 32 cols
    const int brow = blockIdx.y * 128;
    const int bcol = blockIdx.x * 128;

    const int NIT = Kp / 32;

    // gmem load mapping (16B chunks)
    // A: 128 rows x 4 chunks; B: 32 rows x 16 chunks; 512 chunks each, 2/thread.
    auto prefetch = [&](int it, int buf) {
#pragma unroll
        for (int i = 0; i < 2; i++) {
            int c = tid + 256 * i;
            int ar = c >> 2, ac = (c & 3) * 8;
            unsigned sa = (unsigned)__cvta_generic_to_shared(
                &As[buf][ar * APAD + ac]);
            cp16(sa, A + (size_t)(brow + ar) * Kp + it * 32 + ac);
            int br = c >> 4, bc2 = (c & 15) * 8;
            unsigned sb = (unsigned)__cvta_generic_to_shared(
                &Bs[buf][br * BPAD + bc2]);
            cp16(sb, B + (size_t)(it * 32 + br) * N + bcol + bc2);
        }
    };

    float acc[4][4][4];
#pragma unroll
    for (int i = 0; i < 4; i++)
#pragma unroll
        for (int j = 0; j < 4; j++)
#pragma unroll
            for (int t = 0; t < 4; t++) acc[i][j][t] = 0.0f;

    prefetch(0, 0); cp_commit();
    prefetch(1, 1); cp_commit();

    const int lr = lane & 15;        // ldmatrix row select
    const int lc = (lane >> 4) * 8;  // ldmatrix col-block select

    for (int it = 0; it < NIT; it++) {
        cp_wait1();
        __syncthreads();
        const __nv_bfloat16* a = As[it & 1];
        const __nv_bfloat16* b = Bs[it & 1];

#pragma unroll
        for (int kk = 0; kk < 32; kk += 16) {
            unsigned af[4][4], bf[2][4];
#pragma unroll
            for (int mt = 0; mt < 4; mt++) {
                unsigned addr = (unsigned)__cvta_generic_to_shared(
                    &a[(wm * 64 + mt * 16 + lr) * APAD + kk + lc]);
                asm volatile(
                    "ldmatrix.sync.aligned.m8n8.x4.shared.b16 {%0,%1,%2,%3}, [%4];"
                    : "=r"(af[mt][0]), "=r"(af[mt][1]), "=r"(af[mt][2]), "=r"(af[mt][3])
                    : "r"(addr));
            }
#pragma unroll
            for (int nh = 0; nh < 2; nh++) {
                unsigned addr = (unsigned)__cvta_generic_to_shared(
                    &b[(kk + lr) * BPAD + wn * 32 + nh * 16 + lc]);
                asm volatile(
                    "ldmatrix.sync.aligned.m8n8.x4.trans.shared.b16 {%0,%1,%2,%3}, [%4];"
                    : "=r"(bf[nh][0]), "=r"(bf[nh][1]), "=r"(bf[nh][2]), "=r"(bf[nh][3])
                    : "r"(addr));
            }
#pragma unroll
            for (int mt = 0; mt < 4; mt++)
#pragma unroll
                for (int nt = 0; nt < 4; nt++) {
                    unsigned b0 = bf[nt >> 1][(nt & 1) * 2 + 0];
                    unsigned b1 = bf[nt >> 1][(nt & 1) * 2 + 1];
                    asm volatile(
                        "mma.sync.aligned.m16n8k16.row.col.f32.bf16.bf16.f32 "
                        "{%0,%1,%2,%3}, {%4,%5,%6,%7}, {%8,%9}, {%0,%1,%2,%3};"
                        : "+f"(acc[mt][nt][0]), "+f"(acc[mt][nt][1]),
                          "+f"(acc[mt][nt][2]), "+f"(acc[mt][nt][3])
                        : "r"(af[mt][0]), "r"(af[mt][1]), "r"(af[mt][2]), "r"(af[mt][3]),
                          "r"(b0), "r"(b1));
                }
        }
        __syncthreads();
        if (it + 2 < NIT) prefetch(it + 2, it & 1);
        cp_commit();
    }

    // epilogue
#pragma unroll
    for (int mt = 0; mt < 4; mt++) {
        int r0 = brow + wm * 64 + mt * 16 + (lane >> 2);
#pragma unroll
        for (int nt = 0; nt < 4; nt++) {
            int cc = bcol + wn * 32 + nt * 8 + (lane & 3) * 2;
            *(float2*)(C + (size_t)r0 * N + cc) =
                make_float2(acc[mt][nt][0], acc[mt][nt][1]);
            *(float2*)(C + (size_t)(r0 + 8) * N + cc) =
                make_float2(acc[mt][nt][2], acc[mt][nt][3]);
        }
    }
}

// ---------------------------------------------------------------------------
// RoPE (in place on g_q / g_k). One thread per rotation pair.
// ---------------------------------------------------------------------------
__global__ void rope_kernel(float* __restrict__ q, float* __restrict__ k,
                            const float* __restrict__ cosp,
                            const float* __restrict__ sinp) {
    const int HALF = HD / 2;
    const int total_q = TOKENS * NH * HALF;
    const int total   = total_q + TOKENS * NKV * HALF;
    int idx = blockIdx.x * blockDim.x + threadIdx.x;
    if (idx >= total) return;

    float* ptr;
    int tok, i;
    if (idx < total_q) {
        i = idx % HALF;
        int t = idx / HALF;
        int head = t % NH;
        tok = t / NH;
        ptr = q + ((size_t)tok * NH + head) * HD;
    } else {
        int id2 = idx - total_q;
        i = id2 % HALF;
        int t = id2 / HALF;
        int head = t % NKV;
        tok = t / NKV;
        ptr = k + ((size_t)tok * NKV + head) * HD;
    }
    int pos = tok & (SEQ - 1);
    float c0 = cosp[pos * HD + i];
    float s0 = sinp[pos * HD + i];
    float c1 = cosp[pos * HD + HALF + i];
    float s1 = sinp[pos * HD + HALF + i];
    float a = ptr[i];
    float b = ptr[i + HALF];
    ptr[i]        = a * c0 - b * s0;
    ptr[i + HALF] = b * c1 + a * s1;
}

// ---------------------------------------------------------------------------
// Causal GQA flash attention, fp32 (unchanged from R1).
// ---------------------------------------------------------------------------
__global__ __launch_bounds__(256) void attn_kernel(
    const float* __restrict__ q, const float* __restrict__ k,
    const float* __restrict__ v, float* __restrict__ o) {
    __shared__ float Qs[64 * 64];
    __shared__ float Ks[64 * 64];
    __shared__ float Vs[64 * 64];

    const int qt   = blockIdx.x;
    const int h    = blockIdx.y;
    const int b    = blockIdx.z;
    const int kvh  = h >> 2;
    const int tid  = threadIdx.x;
    const int w    = tid >> 5;
    const int lane = tid & 31;
    const int c0   = lane;
    const int c1   = lane + 32;

    const float scale = 0.125f;

    const float* qbase = q + ((size_t)(b * SEQ + qt * 64) * NH + h) * HD;
    for (int idx = tid; idx < 64 * 64; idx += 256) {
        int r = idx >> 6, d = idx & 63;
        Qs[idx] = qbase[(size_t)r * (NH * HD) + d] * scale;
    }

    float O0[8], O1[8], m[8], l[8];
#pragma unroll
    for (int r = 0; r < 8; r++) {
        O0[r] = 0.0f; O1[r] = 0.0f; m[r] = -1e30f; l[r] = 0.0f;
    }

    for (int kt = 0; kt <= qt; kt++) {
        __syncthreads();
        const float* kbase = k + ((size_t)(b * SEQ + kt * 64) * NKV + kvh) * HD;
        const float* vbase = v + ((size_t)(b * SEQ + kt * 64) * NKV + kvh) * HD;
        for (int idx = tid; idx < 64 * 64; idx += 256) {
            int r = idx >> 6, d = idx & 63;
            Ks[r * 64 + (d ^ r)] = kbase[(size_t)r * (NKV * HD) + d];
            Vs[idx]              = vbase[(size_t)r * (NKV * HD) + d];
        }
        __syncthreads();

        float S0[8], S1[8];
#pragma unroll
        for (int r = 0; r < 8; r++) { S0[r] = 0.0f; S1[r] = 0.0f; }
        for (int d = 0; d < 64; d++) {
            float k0v = Ks[c0 * 64 + (d ^ c0)];
            float k1v = Ks[c1 * 64 + (d ^ c1)];
#pragma unroll
            for (int r = 0; r < 8; r++) {
                float qv = Qs[(w * 8 + r) * 64 + d];
                S0[r] += qv * k0v;
                S1[r] += qv * k1v;
            }
        }

#pragma unroll
        for (int r = 0; r < 8; r++) {
            int row = w * 8 + r;
            if (kt == qt) {
                if (c0 > row) S0[r] = -1e30f;
                if (c1 > row) S1[r] = -1e30f;
            }
            float mr = fmaxf(S0[r], S1[r]);
#pragma unroll
            for (int off = 16; off > 0; off >>= 1)
                mr = fmaxf(mr, __shfl_xor_sync(0xffffffffu, mr, off));
            float mn   = fmaxf(m[r], mr);
            float p0   = __expf(S0[r] - mn);
            float p1   = __expf(S1[r] - mn);
            float corr = __expf(m[r] - mn);
            float ls   = p0 + p1;
#pragma unroll
            for (int off = 16; off > 0; off >>= 1)
                ls += __shfl_xor_sync(0xffffffffu, ls, off);
            l[r]  = l[r] * corr + ls;
            O0[r] *= corr;
            O1[r] *= corr;
            m[r]  = mn;
            S0[r] = p0;
            S1[r] = p1;
        }

        __syncthreads();
        float* Ps = Ks;
#pragma unroll
        for (int r = 0; r < 8; r++) {
            Ps[(w * 8 + r) * 64 + c0] = S0[r];
            Ps[(w * 8 + r) * 64 + c1] = S1[r];
        }
        __syncthreads();

        for (int j = 0; j < 64; j++) {
            float v0 = Vs[j * 64 + c0];
            float v1 = Vs[j * 64 + c1];
#pragma unroll
            for (int r = 0; r < 8; r++) {
                float p = Ps[(w * 8 + r) * 64 + j];
                O0[r] += p * v0;
                O1[r] += p * v1;
            }
        }
    }

    float* obase = o + ((size_t)(b * SEQ + qt * 64) * NH + h) * HD;
#pragma unroll
    for (int r = 0; r < 8; r++) {
        float inv = 1.0f / l[r];
        obase[(size_t)(w * 8 + r) * (NH * HD) + c0] = O0[r] * inv;
        obase[(size_t)(w * 8 + r) * (NH * HD) + c1] = O1[r] * inv;
    }
}

// ---------------------------------------------------------------------------
extern "C" void kernel_launch(void* const* d_in, const int* in_sizes, int n_in,
                              void* d_out, int out_size) {
    const float* x    = (const float*)d_in[0];
    const float* cosp = (const float*)d_in[1];
    const float* sinp = (const float*)d_in[2];
    const float* wq   = (const float*)d_in[3];
    const float* wk   = (const float*)d_in[4];
    const float* wv   = (const float*)d_in[5];
    const float* wo   = (const float*)d_in[6];
    float* out        = (float*)d_out;

    float *pq, *pk, *pv, *po;
    __nv_bfloat16 *pxs, *pos, *pwqs, *pwks, *pwvs, *pwos;
    cudaGetSymbolAddress((void**)&pq, g_q);
    cudaGetSymbolAddress((void**)&pk, g_k);
    cudaGetSymbolAddress((void**)&pv, g_v);
    cudaGetSymbolAddress((void**)&po, g_o);
    cudaGetSymbolAddress((void**)&pxs, g_xs);
    cudaGetSymbolAddress((void**)&pos, g_os);
    cudaGetSymbolAddress((void**)&pwqs, g_wqs);
    cudaGetSymbolAddress((void**)&pwks, g_wks);
    cudaGetSymbolAddress((void**)&pwvs, g_wvs);
    cudaGetSymbolAddress((void**)&pwos, g_wos);

    // bf16x3 splits
    {
        int t1 = TOKENS * DMODEL / 4;
        split_A_kernel<<<(t1 + 255) / 256, 256>>>(x, pxs, TOKENS, DMODEL);
        int t2 = DMODEL * DMODEL / 4;
        split_B_kernel<<<(t2 + 255) / 256, 256>>>(wq, pwqs, DMODEL, DMODEL);
        int t3 = DMODEL * (NKV * HD) / 4;
        split_B_kernel<<<(t3 + 255) / 256, 256>>>(wk, pwks, DMODEL, NKV * HD);
        split_B_kernel<<<(t3 + 255) / 256, 256>>>(wv, pwvs, DMODEL, NKV * HD);
        split_B_kernel<<<(t2 + 255) / 256, 256>>>(wo, pwos, NH * HD, DMODEL);
    }

    // Projections (tensor core bf16x3)
    bgemm_kernel<<<dim3(DMODEL / 128, TOKENS / 128), 256>>>(
        pxs, pwqs, pq, TOKENS, NH * HD, KP);
    bgemm_kernel<<<dim3((NKV * HD) / 128, TOKENS / 128), 256>>>(
        pxs, pwks, pk, TOKENS, NKV * HD, KP);
    bgemm_kernel<<<dim3((NKV * HD) / 128, TOKENS / 128), 256>>>(
        pxs, pwvs, pv, TOKENS, NKV * HD, KP);

    // RoPE
    {
        int total = TOKENS * NH * (HD / 2) + TOKENS * NKV * (HD / 2);
        rope_kernel<<<(total + 255) / 256, 256>>>(pq, pk, cosp, sinp);
    }

    // Attention (fp32)
    attn_kernel<<<dim3(SEQ / 64, NH, BATCH), 256>>>(pq, pk, pv, po);

    // Output projection: split attention output, then tensor-core GEMM
    {
        int t1 = TOKENS * DMODEL / 4;
        split_A_kernel<<<(t1 + 255) / 256, 256>>>(po, pos, TOKENS, DMODEL);
    }
    bgemm_kernel<<<dim3(DMODEL / 128, TOKENS / 128), 256>>>(
        pos, pwos, out, TOKENS, DMODEL, KP);
}

// round 3
// speedup vs baseline: 2.9649x; 1.8565x over previous
#include <cuda_runtime.h>
#include <cuda_bf16.h>
#include <math.h>

#define BATCH 2
#define SEQ 2048
#define DMODEL 2048
#define NH 32
#define NKV 8
#define HD 64
#define TOKENS (BATCH * SEQ) /* 4096 */
#define KP (3 * DMODEL)      /* 6144 expanded-K for bf16x3 */

// ---------------- scratch (device globals; no cudaMalloc allowed) ----------
__device__ float g_q[TOKENS * NH * HD];
__device__ float g_k[TOKENS * NKV * HD];
__device__ float g_v[TOKENS * NKV * HD];

__device__ __nv_bfloat16 g_q2[TOKENS * NH * 128];   // roped q  [hi|lo]
__device__ __nv_bfloat16 g_k2[TOKENS * NKV * 128];  // roped k  [hi|lo]
__device__ __nv_bfloat16 g_v2[TOKENS * NKV * 128];  // v        [hi|lo]

__device__ __nv_bfloat16 g_xs[TOKENS * KP];         // split(x)   [M, 3K]
__device__ __nv_bfloat16 g_os[TOKENS * KP];         // attn out, pre-split
__device__ __nv_bfloat16 g_wqs[KP * DMODEL];
__device__ __nv_bfloat16 g_wks[KP * (NKV * HD)];
__device__ __nv_bfloat16 g_wvs[KP * (NKV * HD)];
__device__ __nv_bfloat16 g_wos[KP * DMODEL];

// ---------------------------------------------------------------------------
// bf16x3 split kernels. A: [M,K]->[M,3K]=[hi|lo|hi]; B: [K,N]->[3K,N]=[hi;hi;lo]
// ---------------------------------------------------------------------------
__global__ void split_A_kernel(const float* __restrict__ in,
                               __nv_bfloat16* __restrict__ out,
                               int M, int K) {
    int idx = blockIdx.x * blockDim.x + threadIdx.x;
    int total = M * K / 4;
    if (idx >= total) return;
    int m = idx / (K / 4);
    int c = (idx % (K / 4)) * 4;
    float4 v = *(const float4*)(in + (size_t)m * K + c);
    __nv_bfloat16 h[4], l[4];
    float vv[4] = {v.x, v.y, v.z, v.w};
#pragma unroll
    for (int i = 0; i < 4; i++) {
        h[i] = __float2bfloat16_rn(vv[i]);
        l[i] = __float2bfloat16_rn(vv[i] - __bfloat162float(h[i]));
    }
    uint2 hp, lp;
    unsigned short* hs = (unsigned short*)&hp;
    unsigned short* ls = (unsigned short*)&lp;
#pragma unroll
    for (int i = 0; i < 4; i++) { hs[i] = *(unsigned short*)&h[i]; ls[i] = *(unsigned short*)&l[i]; }
    size_t base = (size_t)m * (3 * K);
    *(uint2*)(out + base + c)         = hp;
    *(uint2*)(out + base + K + c)     = lp;
    *(uint2*)(out + base + 2 * K + c) = hp;
}

__global__ void split_B_kernel(const float* __restrict__ in,
                               __nv_bfloat16* __restrict__ out,
                               int K, int N) {
    int idx = blockIdx.x * blockDim.x + threadIdx.x;
    int total = K * N / 4;
    if (idx >= total) return;
    int r = idx / (N / 4);
    int c = (idx % (N / 4)) * 4;
    float4 v = *(const float4*)(in + (size_t)r * N + c);
    __nv_bfloat16 h[4], l[4];
    float vv[4] = {v.x, v.y, v.z, v.w};
#pragma unroll
    for (int i = 0; i < 4; i++) {
        h[i] = __float2bfloat16_rn(vv[i]);
        l[i] = __float2bfloat16_rn(vv[i] - __bfloat162float(h[i]));
    }
    uint2 hp, lp;
    unsigned short* hs = (unsigned short*)&hp;
    unsigned short* ls = (unsigned short*)&lp;
#pragma unroll
    for (int i = 0; i < 4; i++) { hs[i] = *(unsigned short*)&h[i]; ls[i] = *(unsigned short*)&l[i]; }
    *(uint2*)(out + (size_t)r * N + c)           = hp;
    *(uint2*)(out + (size_t)(K + r) * N + c)     = hp;
    *(uint2*)(out + (size_t)(2 * K + r) * N + c) = lp;
}

// ---------------------------------------------------------------------------
// mma / ldmatrix helpers
// ---------------------------------------------------------------------------
__device__ __forceinline__ void mma16816(float* c, const unsigned* a,
                                         unsigned b0, unsigned b1) {
    asm volatile(
        "mma.sync.aligned.m16n8k16.row.col.f32.bf16.bf16.f32 "
        "{%0,%1,%2,%3}, {%4,%5,%6,%7}, {%8,%9}, {%0,%1,%2,%3};"
        : "+f"(c[0]), "+f"(c[1]), "+f"(c[2]), "+f"(c[3])
        : "r"(a[0]), "r"(a[1]), "r"(a[2]), "r"(a[3]), "r"(b0), "r"(b1));
}
__device__ __forceinline__ void ldmx4(unsigned* r, const void* p) {
    unsigned addr = (unsigned)__cvta_generic_to_shared(p);
    asm volatile("ldmatrix.sync.aligned.m8n8.x4.shared.b16 {%0,%1,%2,%3}, [%4];"
                 : "=r"(r[0]), "=r"(r[1]), "=r"(r[2]), "=r"(r[3]) : "r"(addr));
}
__device__ __forceinline__ void ldmx4t(unsigned* r, const void* p) {
    unsigned addr = (unsigned)__cvta_generic_to_shared(p);
    asm volatile("ldmatrix.sync.aligned.m8n8.x4.trans.shared.b16 {%0,%1,%2,%3}, [%4];"
                 : "=r"(r[0]), "=r"(r[1]), "=r"(r[2]), "=r"(r[3]) : "r"(addr));
}
__device__ __forceinline__ unsigned packbf2(float a, float b) {
    __nv_bfloat162 h = __floats2bfloat162_rn(a, b);
    return *(unsigned*)&h;
}

// ---------------------------------------------------------------------------
// bf16 tensor-core GEMM (unchanged from R2): C = A[M,Kp] @ B[Kp,N], fp32 out.
// ---------------------------------------------------------------------------
#define APAD 40
#define BPAD 136

__device__ __forceinline__ void cp16(unsigned s, const void* g) {
    asm volatile("cp.async.cg.shared.global [%0], [%1], 16;\n" :: "r"(s), "l"(g));
}
__device__ __forceinline__ void cp_commit() {
    asm volatile("cp.async.commit_group;\n");
}
__device__ __forceinline__ void cp_wait1() {
    asm volatile("cp.async.wait_group 1;\n");
}

__global__ __launch_bounds__(256) void bgemm_kernel(
    const __nv_bfloat16* __restrict__ A,
    const __nv_bfloat16* __restrict__ B,
    float* __restrict__ C,
    int M, int N, int Kp) {
    __shared__ __nv_bfloat16 As[2][128 * APAD];
    __shared__ __nv_bfloat16 Bs[2][32 * BPAD];

    const int tid  = threadIdx.x;
    const int lane = tid & 31;
    const int wid  = tid >> 5;
    const int wm   = wid >> 2;
    const int wn   = wid & 3;
    const int brow = blockIdx.y * 128;
    const int bcol = blockIdx.x * 128;
    const int NIT  = Kp / 32;

    auto prefetch = [&](int it, int buf) {
#pragma unroll
        for (int i = 0; i < 2; i++) {
            int c = tid + 256 * i;
            int ar = c >> 2, ac = (c & 3) * 8;
            unsigned sa = (unsigned)__cvta_generic_to_shared(&As[buf][ar * APAD + ac]);
            cp16(sa, A + (size_t)(brow + ar) * Kp + it * 32 + ac);
            int br = c >> 4, bc2 = (c & 15) * 8;
            unsigned sb = (unsigned)__cvta_generic_to_shared(&Bs[buf][br * BPAD + bc2]);
            cp16(sb, B + (size_t)(it * 32 + br) * N + bcol + bc2);
        }
    };

    float acc[4][4][4];
#pragma unroll
    for (int i = 0; i < 4; i++)
#pragma unroll
        for (int j = 0; j < 4; j++)
#pragma unroll
            for (int t = 0; t < 4; t++) acc[i][j][t] = 0.0f;

    prefetch(0, 0); cp_commit();
    prefetch(1, 1); cp_commit();

    const int lr = lane & 15;
    const int lc = (lane >> 4) * 8;

    for (int it = 0; it < NIT; it++) {
        cp_wait1();
        __syncthreads();
        const __nv_bfloat16* a = As[it & 1];
        const __nv_bfloat16* b = Bs[it & 1];

#pragma unroll
        for (int kk = 0; kk < 32; kk += 16) {
            unsigned af[4][4], bf[2][4];
#pragma unroll
            for (int mt = 0; mt < 4; mt++)
                ldmx4(af[mt], &a[(wm * 64 + mt * 16 + lr) * APAD + kk + lc]);
#pragma unroll
            for (int nh = 0; nh < 2; nh++)
                ldmx4t(bf[nh], &b[(kk + lr) * BPAD + wn * 32 + nh * 16 + lc]);
#pragma unroll
            for (int mt = 0; mt < 4; mt++)
#pragma unroll
                for (int nt = 0; nt < 4; nt++)
                    mma16816(acc[mt][nt], af[mt],
                             bf[nt >> 1][(nt & 1) * 2 + 0],
                             bf[nt >> 1][(nt & 1) * 2 + 1]);
        }
        __syncthreads();
        if (it + 2 < NIT) prefetch(it + 2, it & 1);
        cp_commit();
    }

#pragma unroll
    for (int mt = 0; mt < 4; mt++) {
        int r0 = brow + wm * 64 + mt * 16 + (lane >> 2);
#pragma unroll
        for (int nt = 0; nt < 4; nt++) {
            int cc = bcol + wn * 32 + nt * 8 + (lane & 3) * 2;
            *(float2*)(C + (size_t)r0 * N + cc) =
                make_float2(acc[mt][nt][0], acc[mt][nt][1]);
            *(float2*)(C + (size_t)(r0 + 8) * N + cc) =
                make_float2(acc[mt][nt][2], acc[mt][nt][3]);
        }
    }
}

// ---------------------------------------------------------------------------
// RoPE + bf16 hi/lo split.  q scaled by 1/sqrt(HD).  One thread per pair.
// out layout per (tok,head): 128 bf16 = [hi(64) | lo(64)].
// ---------------------------------------------------------------------------
__global__ void rope_split_kernel(const float* __restrict__ q,
                                  const float* __restrict__ k,
                                  const float* __restrict__ cosp,
                                  const float* __restrict__ sinp,
                                  __nv_bfloat16* __restrict__ q2,
                                  __nv_bfloat16* __restrict__ k2) {
    const int HALF = HD / 2;
    const int total_q = TOKENS * NH * HALF;
    const int total   = total_q + TOKENS * NKV * HALF;
    int idx = blockIdx.x * blockDim.x + threadIdx.x;
    if (idx >= total) return;

    const float* src;
    __nv_bfloat16* dst;
    int tok, i;
    float scale;
    if (idx < total_q) {
        i = idx % HALF;
        int t = idx / HALF;
        int head = t % NH;
        tok = t / NH;
        src = q + ((size_t)tok * NH + head) * HD;
        dst = q2 + ((size_t)tok * NH + head) * 128;
        scale = 0.125f;
    } else {
        int id2 = idx - total_q;
        i = id2 % HALF;
        int t = id2 / HALF;
        int head = t % NKV;
        tok = t / NKV;
        src = k + ((size_t)tok * NKV + head) * HD;
        dst = k2 + ((size_t)tok * NKV + head) * 128;
        scale = 1.0f;
    }
    int pos = tok & (SEQ - 1);
    float c0 = cosp[pos * HD + i];
    float s0 = sinp[pos * HD + i];
    float c1 = cosp[pos * HD + HALF + i];
    float s1 = sinp[pos * HD + HALF + i];
    float a = src[i];
    float b = src[i + HALF];
    float o0 = (a * c0 - b * s0) * scale;
    float o1 = (b * c1 + a * s1) * scale;
    __nv_bfloat16 h0 = __float2bfloat16_rn(o0);
    __nv_bfloat16 h1 = __float2bfloat16_rn(o1);
    dst[i]              = h0;
    dst[i + HALF]       = h1;
    dst[64 + i]         = __float2bfloat16_rn(o0 - __bfloat162float(h0));
    dst[64 + i + HALF]  = __float2bfloat16_rn(o1 - __bfloat162float(h1));
}

__global__ void vsplit_kernel(const float* __restrict__ v,
                              __nv_bfloat16* __restrict__ v2) {
    int idx = blockIdx.x * blockDim.x + threadIdx.x;
    if (idx >= TOKENS * NKV * HD) return;
    int d  = idx % HD;
    int th = idx / HD;   // tok*NKV + kvh
    float val = v[idx];
    __nv_bfloat16 h = __float2bfloat16_rn(val);
    v2[(size_t)th * 128 + d]      = h;
    v2[(size_t)th * 128 + 64 + d] = __float2bfloat16_rn(val - __bfloat162float(h));
}

// ---------------------------------------------------------------------------
// Tensor-core causal GQA flash attention, bf16x3 compensated.
// Grid: (SEQ/64, NH, BATCH).  128 threads = 4 warps; warp w owns rows 16w..16w+15.
// Writes output pre-split [hi|lo|hi] into g_os[tok][KP].
// ---------------------------------------------------------------------------
__global__ __launch_bounds__(128) void attn_kernel(
    const __nv_bfloat16* __restrict__ q2,
    const __nv_bfloat16* __restrict__ k2,
    const __nv_bfloat16* __restrict__ v2,
    __nv_bfloat16* __restrict__ os) {
    __shared__ __nv_bfloat16 Ks[64][136];  // also Q staging
    __shared__ __nv_bfloat16 Vs[64][136];

    const int qt   = blockIdx.x;
    const int h    = blockIdx.y;
    const int b    = blockIdx.z;
    const int kvh  = h >> 2;
    const int tid  = threadIdx.x;
    const int w    = tid >> 5;
    const int lane = tid & 31;
    const int gid  = lane >> 2;
    const int tig  = lane & 3;

    // ---- stage Q tile through Ks, grab frags into registers ----
    {
        const __nv_bfloat16* qb = q2 + ((size_t)(b * SEQ + qt * 64) * NH + h) * 128;
        for (int i = tid; i < 64 * 16; i += 128) {
            int r = i >> 4, g = i & 15;
            *(uint4*)&Ks[r][g * 8] = *(const uint4*)(qb + (size_t)r * NH * 128 + g * 8);
        }
    }
    __syncthreads();
    unsigned qf[8][4];  // chunks 0-3 = Qh, 4-7 = Ql
    {
        const int lr = lane & 15, lc = (lane >> 4) * 8;
#pragma unroll
        for (int kc = 0; kc < 8; kc++)
            ldmx4(qf[kc], &Ks[w * 16 + lr][kc * 16 + lc]);
    }

    float O[8][4];
#pragma unroll
    for (int nf = 0; nf < 8; nf++)
#pragma unroll
        for (int t = 0; t < 4; t++) O[nf][t] = 0.0f;
    float m0 = -1e30f, m1 = -1e30f, l0 = 0.0f, l1 = 0.0f;

    // b-frag (non-trans) address offsets for K
    const int krow = (lane & 7) + ((lane & 16) >> 1);
    const int kcol = (lane & 8);
    // trans ldmatrix offsets for V
    const int vlr = lane & 15, vlc = (lane >> 4) * 8;

    for (int kt = 0; kt <= qt; kt++) {
        __syncthreads();  // previous iter done with Ks/Vs (and Q frags grabbed)
        {
            const __nv_bfloat16* kb = k2 + ((size_t)(b * SEQ + kt * 64) * NKV + kvh) * 128;
            const __nv_bfloat16* vb = v2 + ((size_t)(b * SEQ + kt * 64) * NKV + kvh) * 128;
            for (int i = tid; i < 64 * 16; i += 128) {
                int r = i >> 4, g = i & 15;
                *(uint4*)&Ks[r][g * 8] = *(const uint4*)(kb + (size_t)r * NKV * 128 + g * 8);
                *(uint4*)&Vs[r][g * 8] = *(const uint4*)(vb + (size_t)r * NKV * 128 + g * 8);
            }
        }
        __syncthreads();

        // ---- S = QhKh + QlKh + QhKl ----
        float S[8][4];
#pragma unroll
        for (int nf = 0; nf < 8; nf++)
#pragma unroll
            for (int t = 0; t < 4; t++) S[nf][t] = 0.0f;

#pragma unroll
        for (int ng = 0; ng < 4; ng++) {
#pragma unroll
            for (int kc = 0; kc < 4; kc++) {
                unsigned kb[4];
                ldmx4(kb, &Ks[ng * 16 + krow][kc * 16 + kcol]);  // Kh
                mma16816(S[2 * ng],     qf[kc],     kb[0], kb[1]);
                mma16816(S[2 * ng + 1], qf[kc],     kb[2], kb[3]);
                mma16816(S[2 * ng],     qf[kc + 4], kb[0], kb[1]);
                mma16816(S[2 * ng + 1], qf[kc + 4], kb[2], kb[3]);
            }
#pragma unroll
            for (int kc = 0; kc < 4; kc++) {
                unsigned kb[4];
                ldmx4(kb, &Ks[ng * 16 + krow][64 + kc * 16 + kcol]);  // Kl
                mma16816(S[2 * ng],     qf[kc], kb[0], kb[1]);
                mma16816(S[2 * ng + 1], qf[kc], kb[2], kb[3]);
            }
        }

        // ---- causal mask on diagonal tile ----
        if (kt == qt) {
            const int r0 = w * 16 + gid, r1 = r0 + 8;
#pragma unroll
            for (int nf = 0; nf < 8; nf++) {
                int cb = nf * 8 + tig * 2;
                if (cb     > r0) S[nf][0] = -1e30f;
                if (cb + 1 > r0) S[nf][1] = -1e30f;
                if (cb     > r1) S[nf][2] = -1e30f;
                if (cb + 1 > r1) S[nf][3] = -1e30f;
            }
        }

        // ---- online softmax ----
        float mx0 = -1e30f, mx1 = -1e30f;
#pragma unroll
        for (int nf = 0; nf < 8; nf++) {
            mx0 = fmaxf(mx0, fmaxf(S[nf][0], S[nf][1]));
            mx1 = fmaxf(mx1, fmaxf(S[nf][2], S[nf][3]));
        }
        mx0 = fmaxf(mx0, __shfl_xor_sync(0xffffffffu, mx0, 1));
        mx0 = fmaxf(mx0, __shfl_xor_sync(0xffffffffu, mx0, 2));
        mx1 = fmaxf(mx1, __shfl_xor_sync(0xffffffffu, mx1, 1));
        mx1 = fmaxf(mx1, __shfl_xor_sync(0xffffffffu, mx1, 2));
        float mn0 = fmaxf(m0, mx0), mn1 = fmaxf(m1, mx1);
        float corr0 = __expf(m0 - mn0), corr1 = __expf(m1 - mn1);
        float ls0 = 0.0f, ls1 = 0.0f;
#pragma unroll
        for (int nf = 0; nf < 8; nf++) {
            S[nf][0] = __expf(S[nf][0] - mn0);
            S[nf][1] = __expf(S[nf][1] - mn0);
            S[nf][2] = __expf(S[nf][2] - mn1);
            S[nf][3] = __expf(S[nf][3] - mn1);
            ls0 += S[nf][0] + S[nf][1];
            ls1 += S[nf][2] + S[nf][3];
        }
        ls0 += __shfl_xor_sync(0xffffffffu, ls0, 1);
        ls0 += __shfl_xor_sync(0xffffffffu, ls0, 2);
        ls1 += __shfl_xor_sync(0xffffffffu, ls1, 1);
        ls1 += __shfl_xor_sync(0xffffffffu, ls1, 2);
        l0 = l0 * corr0 + ls0;
        l1 = l1 * corr1 + ls1;
        m0 = mn0; m1 = mn1;
#pragma unroll
        for (int nf = 0; nf < 8; nf++) {
            O[nf][0] *= corr0; O[nf][1] *= corr0;
            O[nf][2] *= corr1; O[nf][3] *= corr1;
        }

        // ---- pack P into a-frags, hi + lo ----
        unsigned pha[4][4], pla[4][4];
#pragma unroll
        for (int kc = 0; kc < 4; kc++) {
            float p00 = S[2 * kc][0],     p01 = S[2 * kc][1];
            float p10 = S[2 * kc][2],     p11 = S[2 * kc][3];
            float p20 = S[2 * kc + 1][0], p21 = S[2 * kc + 1][1];
            float p30 = S[2 * kc + 1][2], p31 = S[2 * kc + 1][3];
            pha[kc][0] = packbf2(p00, p01);
            pha[kc][1] = packbf2(p10, p11);
            pha[kc][2] = packbf2(p20, p21);
            pha[kc][3] = packbf2(p30, p31);
            __nv_bfloat162* hp;
            hp = (__nv_bfloat162*)&pha[kc][0];
            pla[kc][0] = packbf2(p00 - __bfloat162float(hp->x), p01 - __bfloat162float(hp->y));
            hp = (__nv_bfloat162*)&pha[kc][1];
            pla[kc][1] = packbf2(p10 - __bfloat162float(hp->x), p11 - __bfloat162float(hp->y));
            hp = (__nv_bfloat162*)&pha[kc][2];
            pla[kc][2] = packbf2(p20 - __bfloat162float(hp->x), p21 - __bfloat162float(hp->y));
            hp = (__nv_bfloat162*)&pha[kc][3];
            pla[kc][3] = packbf2(p30 - __bfloat162float(hp->x), p31 - __bfloat162float(hp->y));
        }

        // ---- O += PhVh + PlVh + PhVl ----
#pragma unroll
        for (int kc = 0; kc < 4; kc++) {
#pragma unroll
            for (int ns = 0; ns < 4; ns++) {
                unsigned vb[4];
                ldmx4t(vb, &Vs[kc * 16 + vlr][ns * 16 + vlc]);  // Vh
                mma16816(O[2 * ns],     pha[kc], vb[0], vb[1]);
                mma16816(O[2 * ns + 1], pha[kc], vb[2], vb[3]);
                mma16816(O[2 * ns],     pla[kc], vb[0], vb[1]);
                mma16816(O[2 * ns + 1], pla[kc], vb[2], vb[3]);
                ldmx4t(vb, &Vs[kc * 16 + vlr][64 + ns * 16 + vlc]);  // Vl
                mma16816(O[2 * ns],     pha[kc], vb[0], vb[1]);
                mma16816(O[2 * ns + 1], pha[kc], vb[2], vb[3]);
            }
        }
    }

    // ---- epilogue: normalize, write pre-split [hi|lo|hi] to os ----
    float inv0 = 1.0f / l0, inv1 = 1.0f / l1;
    size_t t0 = (size_t)(b * SEQ + qt * 64 + w * 16 + gid) * KP;
    size_t t1 = t0 + (size_t)8 * KP;
#pragma unroll
    for (int nf = 0; nf < 8; nf++) {
        int col = h * 64 + nf * 8 + tig * 2;
        float f0 = O[nf][0] * inv0, f1 = O[nf][1] * inv0;
        float f2 = O[nf][2] * inv1, f3 = O[nf][3] * inv1;
        unsigned hi0 = packbf2(f0, f1);
        unsigned hi1 = packbf2(f2, f3);
        __nv_bfloat162* hp0 = (__nv_bfloat162*)&hi0;
        __nv_bfloat162* hp1 = (__nv_bfloat162*)&hi1;
        unsigned lo0 = packbf2(f0 - __bfloat162float(hp0->x), f1 - __bfloat162float(hp0->y));
        unsigned lo1 = packbf2(f2 - __bfloat162float(hp1->x), f3 - __bfloat162float(hp1->y));
        *(unsigned*)(os + t0 + col)            = hi0;
        *(unsigned*)(os + t0 + DMODEL + col)   = lo0;
        *(unsigned*)(os + t0 + 2*DMODEL + col) = hi0;
        *(unsigned*)(os + t1 + col)            = hi1;
        *(unsigned*)(os + t1 + DMODEL + col)   = lo1;
        *(unsigned*)(os + t1 + 2*DMODEL + col) = hi1;
    }
}

// ---------------------------------------------------------------------------
extern "C" void kernel_launch(void* const* d_in, const int* in_sizes, int n_in,
                              void* d_out, int out_size) {
    const float* x    = (const float*)d_in[0];
    const float* cosp = (const float*)d_in[1];
    const float* sinp = (const float*)d_in[2];
    const float* wq   = (const float*)d_in[3];
    const float* wk   = (const float*)d_in[4];
    const float* wv   = (const float*)d_in[5];
    const float* wo   = (const float*)d_in[6];
    float* out        = (float*)d_out;

    float *pq, *pk, *pv;
    __nv_bfloat16 *pq2, *pk2, *pv2, *pxs, *pos, *pwqs, *pwks, *pwvs, *pwos;
    cudaGetSymbolAddress((void**)&pq, g_q);
    cudaGetSymbolAddress((void**)&pk, g_k);
    cudaGetSymbolAddress((void**)&pv, g_v);
    cudaGetSymbolAddress((void**)&pq2, g_q2);
    cudaGetSymbolAddress((void**)&pk2, g_k2);
    cudaGetSymbolAddress((void**)&pv2, g_v2);
    cudaGetSymbolAddress((void**)&pxs, g_xs);
    cudaGetSymbolAddress((void**)&pos, g_os);
    cudaGetSymbolAddress((void**)&pwqs, g_wqs);
    cudaGetSymbolAddress((void**)&pwks, g_wks);
    cudaGetSymbolAddress((void**)&pwvs, g_wvs);
    cudaGetSymbolAddress((void**)&pwos, g_wos);

    // bf16x3 splits
    {
        int t1 = TOKENS * DMODEL / 4;
        split_A_kernel<<<(t1 + 255) / 256, 256>>>(x, pxs, TOKENS, DMODEL);
        int t2 = DMODEL * DMODEL / 4;
        split_B_kernel<<<(t2 + 255) / 256, 256>>>(wq, pwqs, DMODEL, DMODEL);
        int t3 = DMODEL * (NKV * HD) / 4;
        split_B_kernel<<<(t3 + 255) / 256, 256>>>(wk, pwks, DMODEL, NKV * HD);
        split_B_kernel<<<(t3 + 255) / 256, 256>>>(wv, pwvs, DMODEL, NKV * HD);
        split_B_kernel<<<(t2 + 255) / 256, 256>>>(wo, pwos, NH * HD, DMODEL);
    }

    // Projections (tensor core bf16x3)
    bgemm_kernel<<<dim3(DMODEL / 128, TOKENS / 128), 256>>>(
        pxs, pwqs, pq, TOKENS, NH * HD, KP);
    bgemm_kernel<<<dim3((NKV * HD) / 128, TOKENS / 128), 256>>>(
        pxs, pwks, pk, TOKENS, NKV * HD, KP);
    bgemm_kernel<<<dim3((NKV * HD) / 128, TOKENS / 128), 256>>>(
        pxs, pwvs, pv, TOKENS, NKV * HD, KP);

    // RoPE + split to bf16 hi/lo
    {
        int total = TOKENS * NH * (HD / 2) + TOKENS * NKV * (HD / 2);
        rope_split_kernel<<<(total + 255) / 256, 256>>>(pq, pk, cosp, sinp, pq2, pk2);
        int tv = TOKENS * NKV * HD;
        vsplit_kernel<<<(tv + 255) / 256, 256>>>(pv, pv2);
    }

    // Attention (tensor core, bf16x3 compensated) -> pre-split output
    attn_kernel<<<dim3(SEQ / 64, NH, BATCH), 128>>>(pq2, pk2, pv2, pos);

    // Output projection
    bgemm_kernel<<<dim3(DMODEL / 128, TOKENS / 128), 256>>>(
        pos, pwos, out, TOKENS, DMODEL, KP);
}

// round 4
// speedup vs baseline: 3.8820x; 1.3093x over previous
#include <cuda_runtime.h>
#include <cuda_bf16.h>
#include <cuda_fp16.h>
#include <math.h>

#define BATCH 2
#define SEQ 2048
#define DMODEL 2048
#define NH 32
#define NKV 8
#define HD 64
#define TOKENS (BATCH * SEQ) /* 4096 */
#define KP2 (2 * DMODEL)     /* 4096 expanded-K for fp16x2 */

// ---------------- scratch (device globals; no cudaMalloc allowed) ----------
__device__ float g_q[TOKENS * NH * HD];
__device__ float g_k[TOKENS * NKV * HD];
__device__ float g_v[TOKENS * NKV * HD];

__device__ __nv_bfloat16 g_q2[TOKENS * NH * 128];   // roped q  [hi|lo] bf16
__device__ __nv_bfloat16 g_k2[TOKENS * NKV * 128];  // roped k  [hi|lo] bf16
__device__ __nv_bfloat16 g_v2[TOKENS * NKV * 128];  // v        [hi|lo] bf16

__device__ __half g_xs[TOKENS * KP2];               // split(x)  [M, 2K] fp16
__device__ __half g_os[TOKENS * KP2];               // attn out, pre-split fp16
__device__ __half g_wqs[KP2 * DMODEL];
__device__ __half g_wks[KP2 * (NKV * HD)];
__device__ __half g_wvs[KP2 * (NKV * HD)];
__device__ __half g_wos[KP2 * DMODEL];

// ---------------------------------------------------------------------------
// fp16x2 split kernels.
// A: [M,K] -> [M,2K] = [hi | lo]  (A-residual captured)
// B: [K,N] -> [2K,N] = [hi ; hi]  (B-residual dropped; err ~2^-12)
// ---------------------------------------------------------------------------
__global__ void split_A_kernel(const float* __restrict__ in,
                               __half* __restrict__ out,
                               int M, int K) {
    int idx = blockIdx.x * blockDim.x + threadIdx.x;
    int total = M * K / 4;
    if (idx >= total) return;
    int m = idx / (K / 4);
    int c = (idx % (K / 4)) * 4;
    float4 v = *(const float4*)(in + (size_t)m * K + c);
    float vv[4] = {v.x, v.y, v.z, v.w};
    __half h[4], l[4];
#pragma unroll
    for (int i = 0; i < 4; i++) {
        h[i] = __float2half_rn(vv[i]);
        l[i] = __float2half_rn(vv[i] - __half2float(h[i]));
    }
    uint2 hp, lp;
    unsigned short* hs = (unsigned short*)&hp;
    unsigned short* ls = (unsigned short*)&lp;
#pragma unroll
    for (int i = 0; i < 4; i++) { hs[i] = *(unsigned short*)&h[i]; ls[i] = *(unsigned short*)&l[i]; }
    size_t base = (size_t)m * (2 * K);
    *(uint2*)(out + base + c)     = hp;
    *(uint2*)(out + base + K + c) = lp;
}

__global__ void split_B_kernel(const float* __restrict__ in,
                               __half* __restrict__ out,
                               int K, int N) {
    int idx = blockIdx.x * blockDim.x + threadIdx.x;
    int total = K * N / 4;
    if (idx >= total) return;
    int r = idx / (N / 4);
    int c = (idx % (N / 4)) * 4;
    float4 v = *(const float4*)(in + (size_t)r * N + c);
    float vv[4] = {v.x, v.y, v.z, v.w};
    __half h[4];
#pragma unroll
    for (int i = 0; i < 4; i++) h[i] = __float2half_rn(vv[i]);
    uint2 hp;
    unsigned short* hs = (unsigned short*)&hp;
#pragma unroll
    for (int i = 0; i < 4; i++) hs[i] = *(unsigned short*)&h[i];
    *(uint2*)(out + (size_t)r * N + c)       = hp;
    *(uint2*)(out + (size_t)(K + r) * N + c) = hp;
}

// ---------------------------------------------------------------------------
// mma / ldmatrix helpers
// ---------------------------------------------------------------------------
__device__ __forceinline__ void mma16816(float* c, const unsigned* a,
                                         unsigned b0, unsigned b1) {
    asm volatile(
        "mma.sync.aligned.m16n8k16.row.col.f32.bf16.bf16.f32 "
        "{%0,%1,%2,%3}, {%4,%5,%6,%7}, {%8,%9}, {%0,%1,%2,%3};"
        : "+f"(c[0]), "+f"(c[1]), "+f"(c[2]), "+f"(c[3])
        : "r"(a[0]), "r"(a[1]), "r"(a[2]), "r"(a[3]), "r"(b0), "r"(b1));
}
__device__ __forceinline__ void mma16816h(float* c, const unsigned* a,
                                          unsigned b0, unsigned b1) {
    asm volatile(
        "mma.sync.aligned.m16n8k16.row.col.f32.f16.f16.f32 "
        "{%0,%1,%2,%3}, {%4,%5,%6,%7}, {%8,%9}, {%0,%1,%2,%3};"
        : "+f"(c[0]), "+f"(c[1]), "+f"(c[2]), "+f"(c[3])
        : "r"(a[0]), "r"(a[1]), "r"(a[2]), "r"(a[3]), "r"(b0), "r"(b1));
}
__device__ __forceinline__ void ldmx4(unsigned* r, const void* p) {
    unsigned addr = (unsigned)__cvta_generic_to_shared(p);
    asm volatile("ldmatrix.sync.aligned.m8n8.x4.shared.b16 {%0,%1,%2,%3}, [%4];"
                 : "=r"(r[0]), "=r"(r[1]), "=r"(r[2]), "=r"(r[3]) : "r"(addr));
}
__device__ __forceinline__ void ldmx4t(unsigned* r, const void* p) {
    unsigned addr = (unsigned)__cvta_generic_to_shared(p);
    asm volatile("ldmatrix.sync.aligned.m8n8.x4.trans.shared.b16 {%0,%1,%2,%3}, [%4];"
                 : "=r"(r[0]), "=r"(r[1]), "=r"(r[2]), "=r"(r[3]) : "r"(addr));
}
__device__ __forceinline__ unsigned packbf2(float a, float b) {
    __nv_bfloat162 h = __floats2bfloat162_rn(a, b);
    return *(unsigned*)&h;
}
__device__ __forceinline__ unsigned packh2(float a, float b) {
    __half2 h = __floats2half2_rn(a, b);
    return *(unsigned*)&h;
}

// ---------------------------------------------------------------------------
// fp16 tensor-core GEMM: C[M,N] fp32 = A[M,Kp] f16 @ B[Kp,N] f16.
// 128x128 tile, BK=32, 256 threads, warp tile 64x32, cp.async double buffered.
// ---------------------------------------------------------------------------
#define APAD 40
#define BPAD 136

__device__ __forceinline__ void cp16(unsigned s, const void* g) {
    asm volatile("cp.async.cg.shared.global [%0], [%1], 16;\n" :: "r"(s), "l"(g));
}
__device__ __forceinline__ void cp_commit() {
    asm volatile("cp.async.commit_group;\n");
}
__device__ __forceinline__ void cp_wait1() {
    asm volatile("cp.async.wait_group 1;\n");
}

__global__ __launch_bounds__(256) void hgemm_kernel(
    const __half* __restrict__ A,
    const __half* __restrict__ B,
    float* __restrict__ C,
    int M, int N, int Kp) {
    __shared__ __half As[2][128 * APAD];
    __shared__ __half Bs[2][32 * BPAD];

    const int tid  = threadIdx.x;
    const int lane = tid & 31;
    const int wid  = tid >> 5;
    const int wm   = wid >> 2;
    const int wn   = wid & 3;
    const int brow = blockIdx.y * 128;
    const int bcol = blockIdx.x * 128;
    const int NIT  = Kp / 32;

    auto prefetch = [&](int it, int buf) {
#pragma unroll
        for (int i = 0; i < 2; i++) {
            int c = tid + 256 * i;
            int ar = c >> 2, ac = (c & 3) * 8;
            unsigned sa = (unsigned)__cvta_generic_to_shared(&As[buf][ar * APAD + ac]);
            cp16(sa, A + (size_t)(brow + ar) * Kp + it * 32 + ac);
            int br = c >> 4, bc2 = (c & 15) * 8;
            unsigned sb = (unsigned)__cvta_generic_to_shared(&Bs[buf][br * BPAD + bc2]);
            cp16(sb, B + (size_t)(it * 32 + br) * N + bcol + bc2);
        }
    };

    float acc[4][4][4];
#pragma unroll
    for (int i = 0; i < 4; i++)
#pragma unroll
        for (int j = 0; j < 4; j++)
#pragma unroll
            for (int t = 0; t < 4; t++) acc[i][j][t] = 0.0f;

    prefetch(0, 0); cp_commit();
    prefetch(1, 1); cp_commit();

    const int lr = lane & 15;
    const int lc = (lane >> 4) * 8;

    for (int it = 0; it < NIT; it++) {
        cp_wait1();
        __syncthreads();
        const __half* a = As[it & 1];
        const __half* b = Bs[it & 1];

#pragma unroll
        for (int kk = 0; kk < 32; kk += 16) {
            unsigned af[4][4], bf[2][4];
#pragma unroll
            for (int mt = 0; mt < 4; mt++)
                ldmx4(af[mt], &a[(wm * 64 + mt * 16 + lr) * APAD + kk + lc]);
#pragma unroll
            for (int nh = 0; nh < 2; nh++)
                ldmx4t(bf[nh], &b[(kk + lr) * BPAD + wn * 32 + nh * 16 + lc]);
#pragma unroll
            for (int mt = 0; mt < 4; mt++)
#pragma unroll
                for (int nt = 0; nt < 4; nt++)
                    mma16816h(acc[mt][nt], af[mt],
                              bf[nt >> 1][(nt & 1) * 2 + 0],
                              bf[nt >> 1][(nt & 1) * 2 + 1]);
        }
        __syncthreads();
        if (it + 2 < NIT) prefetch(it + 2, it & 1);
        cp_commit();
    }

#pragma unroll
    for (int mt = 0; mt < 4; mt++) {
        int r0 = brow + wm * 64 + mt * 16 + (lane >> 2);
#pragma unroll
        for (int nt = 0; nt < 4; nt++) {
            int cc = bcol + wn * 32 + nt * 8 + (lane & 3) * 2;
            *(float2*)(C + (size_t)r0 * N + cc) =
                make_float2(acc[mt][nt][0], acc[mt][nt][1]);
            *(float2*)(C + (size_t)(r0 + 8) * N + cc) =
                make_float2(acc[mt][nt][2], acc[mt][nt][3]);
        }
    }
}

// ---------------------------------------------------------------------------
// RoPE + bf16 hi/lo split for attention operands (unchanged).
// ---------------------------------------------------------------------------
__global__ void rope_split_kernel(const float* __restrict__ q,
                                  const float* __restrict__ k,
                                  const float* __restrict__ cosp,
                                  const float* __restrict__ sinp,
                                  __nv_bfloat16* __restrict__ q2,
                                  __nv_bfloat16* __restrict__ k2) {
    const int HALF = HD / 2;
    const int total_q = TOKENS * NH * HALF;
    const int total   = total_q + TOKENS * NKV * HALF;
    int idx = blockIdx.x * blockDim.x + threadIdx.x;
    if (idx >= total) return;

    const float* src;
    __nv_bfloat16* dst;
    int tok, i;
    float scale;
    if (idx < total_q) {
        i = idx % HALF;
        int t = idx / HALF;
        int head = t % NH;
        tok = t / NH;
        src = q + ((size_t)tok * NH + head) * HD;
        dst = q2 + ((size_t)tok * NH + head) * 128;
        scale = 0.125f;
    } else {
        int id2 = idx - total_q;
        i = id2 % HALF;
        int t = id2 / HALF;
        int head = t % NKV;
        tok = t / NKV;
        src = k + ((size_t)tok * NKV + head) * HD;
        dst = k2 + ((size_t)tok * NKV + head) * 128;
        scale = 1.0f;
    }
    int pos = tok & (SEQ - 1);
    float c0 = cosp[pos * HD + i];
    float s0 = sinp[pos * HD + i];
    float c1 = cosp[pos * HD + HALF + i];
    float s1 = sinp[pos * HD + HALF + i];
    float a = src[i];
    float b = src[i + HALF];
    float o0 = (a * c0 - b * s0) * scale;
    float o1 = (b * c1 + a * s1) * scale;
    __nv_bfloat16 h0 = __float2bfloat16_rn(o0);
    __nv_bfloat16 h1 = __float2bfloat16_rn(o1);
    dst[i]              = h0;
    dst[i + HALF]       = h1;
    dst[64 + i]         = __float2bfloat16_rn(o0 - __bfloat162float(h0));
    dst[64 + i + HALF]  = __float2bfloat16_rn(o1 - __bfloat162float(h1));
}

__global__ void vsplit_kernel(const float* __restrict__ v,
                              __nv_bfloat16* __restrict__ v2) {
    int idx = blockIdx.x * blockDim.x + threadIdx.x;
    if (idx >= TOKENS * NKV * HD) return;
    int d  = idx % HD;
    int th = idx / HD;
    float val = v[idx];
    __nv_bfloat16 h = __float2bfloat16_rn(val);
    v2[(size_t)th * 128 + d]      = h;
    v2[(size_t)th * 128 + 64 + d] = __float2bfloat16_rn(val - __bfloat162float(h));
}

// ---------------------------------------------------------------------------
// Tensor-core causal GQA flash attention, bf16x3 compensated (unchanged math).
// Epilogue writes fp16 [hi|lo] into g_os[tok][KP2].
// ---------------------------------------------------------------------------
__global__ __launch_bounds__(128) void attn_kernel(
    const __nv_bfloat16* __restrict__ q2,
    const __nv_bfloat16* __restrict__ k2,
    const __nv_bfloat16* __restrict__ v2,
    __half* __restrict__ os) {
    __shared__ __nv_bfloat16 Ks[64][136];
    __shared__ __nv_bfloat16 Vs[64][136];

    const int qt   = blockIdx.x;
    const int h    = blockIdx.y;
    const int b    = blockIdx.z;
    const int kvh  = h >> 2;
    const int tid  = threadIdx.x;
    const int w    = tid >> 5;
    const int lane = tid & 31;
    const int gid  = lane >> 2;
    const int tig  = lane & 3;

    {
        const __nv_bfloat16* qb = q2 + ((size_t)(b * SEQ + qt * 64) * NH + h) * 128;
        for (int i = tid; i < 64 * 16; i += 128) {
            int r = i >> 4, g = i & 15;
            *(uint4*)&Ks[r][g * 8] = *(const uint4*)(qb + (size_t)r * NH * 128 + g * 8);
        }
    }
    __syncthreads();
    unsigned qf[8][4];
    {
        const int lr = lane & 15, lc = (lane >> 4) * 8;
#pragma unroll
        for (int kc = 0; kc < 8; kc++)
            ldmx4(qf[kc], &Ks[w * 16 + lr][kc * 16 + lc]);
    }

    float O[8][4];
#pragma unroll
    for (int nf = 0; nf < 8; nf++)
#pragma unroll
        for (int t = 0; t < 4; t++) O[nf][t] = 0.0f;
    float m0 = -1e30f, m1 = -1e30f, l0 = 0.0f, l1 = 0.0f;

    const int krow = (lane & 7) + ((lane & 16) >> 1);
    const int kcol = (lane & 8);
    const int vlr = lane & 15, vlc = (lane >> 4) * 8;

    for (int kt = 0; kt <= qt; kt++) {
        __syncthreads();
        {
            const __nv_bfloat16* kb = k2 + ((size_t)(b * SEQ + kt * 64) * NKV + kvh) * 128;
            const __nv_bfloat16* vb = v2 + ((size_t)(b * SEQ + kt * 64) * NKV + kvh) * 128;
            for (int i = tid; i < 64 * 16; i += 128) {
                int r = i >> 4, g = i & 15;
                *(uint4*)&Ks[r][g * 8] = *(const uint4*)(kb + (size_t)r * NKV * 128 + g * 8);
                *(uint4*)&Vs[r][g * 8] = *(const uint4*)(vb + (size_t)r * NKV * 128 + g * 8);
            }
        }
        __syncthreads();

        float S[8][4];
#pragma unroll
        for (int nf = 0; nf < 8; nf++)
#pragma unroll
            for (int t = 0; t < 4; t++) S[nf][t] = 0.0f;

#pragma unroll
        for (int ng = 0; ng < 4; ng++) {
#pragma unroll
            for (int kc = 0; kc < 4; kc++) {
                unsigned kb[4];
                ldmx4(kb, &Ks[ng * 16 + krow][kc * 16 + kcol]);
                mma16816(S[2 * ng],     qf[kc],     kb[0], kb[1]);
                mma16816(S[2 * ng + 1], qf[kc],     kb[2], kb[3]);
                mma16816(S[2 * ng],     qf[kc + 4], kb[0], kb[1]);
                mma16816(S[2 * ng + 1], qf[kc + 4], kb[2], kb[3]);
            }
#pragma unroll
            for (int kc = 0; kc < 4; kc++) {
                unsigned kb[4];
                ldmx4(kb, &Ks[ng * 16 + krow][64 + kc * 16 + kcol]);
                mma16816(S[2 * ng],     qf[kc], kb[0], kb[1]);
                mma16816(S[2 * ng + 1], qf[kc], kb[2], kb[3]);
            }
        }

        if (kt == qt) {
            const int r0 = w * 16 + gid, r1 = r0 + 8;
#pragma unroll
            for (int nf = 0; nf < 8; nf++) {
                int cb = nf * 8 + tig * 2;
                if (cb     > r0) S[nf][0] = -1e30f;
                if (cb + 1 > r0) S[nf][1] = -1e30f;
                if (cb     > r1) S[nf][2] = -1e30f;
                if (cb + 1 > r1) S[nf][3] = -1e30f;
            }
        }

        float mx0 = -1e30f, mx1 = -1e30f;
#pragma unroll
        for (int nf = 0; nf < 8; nf++) {
            mx0 = fmaxf(mx0, fmaxf(S[nf][0], S[nf][1]));
            mx1 = fmaxf(mx1, fmaxf(S[nf][2], S[nf][3]));
        }
        mx0 = fmaxf(mx0, __shfl_xor_sync(0xffffffffu, mx0, 1));
        mx0 = fmaxf(mx0, __shfl_xor_sync(0xffffffffu, mx0, 2));
        mx1 = fmaxf(mx1, __shfl_xor_sync(0xffffffffu, mx1, 1));
        mx1 = fmaxf(mx1, __shfl_xor_sync(0xffffffffu, mx1, 2));
        float mn0 = fmaxf(m0, mx0), mn1 = fmaxf(m1, mx1);
        float corr0 = __expf(m0 - mn0), corr1 = __expf(m1 - mn1);
        float ls0 = 0.0f, ls1 = 0.0f;
#pragma unroll
        for (int nf = 0; nf < 8; nf++) {
            S[nf][0] = __expf(S[nf][0] - mn0);
            S[nf][1] = __expf(S[nf][1] - mn0);
            S[nf][2] = __expf(S[nf][2] - mn1);
            S[nf][3] = __expf(S[nf][3] - mn1);
            ls0 += S[nf][0] + S[nf][1];
            ls1 += S[nf][2] + S[nf][3];
        }
        ls0 += __shfl_xor_sync(0xffffffffu, ls0, 1);
        ls0 += __shfl_xor_sync(0xffffffffu, ls0, 2);
        ls1 += __shfl_xor_sync(0xffffffffu, ls1, 1);
        ls1 += __shfl_xor_sync(0xffffffffu, ls1, 2);
        l0 = l0 * corr0 + ls0;
        l1 = l1 * corr1 + ls1;
        m0 = mn0; m1 = mn1;
#pragma unroll
        for (int nf = 0; nf < 8; nf++) {
            O[nf][0] *= corr0; O[nf][1] *= corr0;
            O[nf][2] *= corr1; O[nf][3] *= corr1;
        }

        unsigned pha[4][4], pla[4][4];
#pragma unroll
        for (int kc = 0; kc < 4; kc++) {
            float p00 = S[2 * kc][0],     p01 = S[2 * kc][1];
            float p10 = S[2 * kc][2],     p11 = S[2 * kc][3];
            float p20 = S[2 * kc + 1][0], p21 = S[2 * kc + 1][1];
            float p30 = S[2 * kc + 1][2], p31 = S[2 * kc + 1][3];
            pha[kc][0] = packbf2(p00, p01);
            pha[kc][1] = packbf2(p10, p11);
            pha[kc][2] = packbf2(p20, p21);
            pha[kc][3] = packbf2(p30, p31);
            __nv_bfloat162* hp;
            hp = (__nv_bfloat162*)&pha[kc][0];
            pla[kc][0] = packbf2(p00 - __bfloat162float(hp->x), p01 - __bfloat162float(hp->y));
            hp = (__nv_bfloat162*)&pha[kc][1];
            pla[kc][1] = packbf2(p10 - __bfloat162float(hp->x), p11 - __bfloat162float(hp->y));
            hp = (__nv_bfloat162*)&pha[kc][2];
            pla[kc][2] = packbf2(p20 - __bfloat162float(hp->x), p21 - __bfloat162float(hp->y));
            hp = (__nv_bfloat162*)&pha[kc][3];
            pla[kc][3] = packbf2(p30 - __bfloat162float(hp->x), p31 - __bfloat162float(hp->y));
        }

#pragma unroll
        for (int kc = 0; kc < 4; kc++) {
#pragma unroll
            for (int ns = 0; ns < 4; ns++) {
                unsigned vb[4];
                ldmx4t(vb, &Vs[kc * 16 + vlr][ns * 16 + vlc]);
                mma16816(O[2 * ns],     pha[kc], vb[0], vb[1]);
                mma16816(O[2 * ns + 1], pha[kc], vb[2], vb[3]);
                mma16816(O[2 * ns],     pla[kc], vb[0], vb[1]);
                mma16816(O[2 * ns + 1], pla[kc], vb[2], vb[3]);
                ldmx4t(vb, &Vs[kc * 16 + vlr][64 + ns * 16 + vlc]);
                mma16816(O[2 * ns],     pha[kc], vb[0], vb[1]);
                mma16816(O[2 * ns + 1], pha[kc], vb[2], vb[3]);
            }
        }
    }

    // ---- epilogue: normalize, write fp16 [hi|lo] to os ----
    float inv0 = 1.0f / l0, inv1 = 1.0f / l1;
    size_t t0 = (size_t)(b * SEQ + qt * 64 + w * 16 + gid) * KP2;
    size_t t1 = t0 + (size_t)8 * KP2;
#pragma unroll
    for (int nf = 0; nf < 8; nf++) {
        int col = h * 64 + nf * 8 + tig * 2;
        float f0 = O[nf][0] * inv0, f1 = O[nf][1] * inv0;
        float f2 = O[nf][2] * inv1, f3 = O[nf][3] * inv1;
        unsigned hi0 = packh2(f0, f1);
        unsigned hi1 = packh2(f2, f3);
        __half2* hp0 = (__half2*)&hi0;
        __half2* hp1 = (__half2*)&hi1;
        unsigned lo0 = packh2(f0 - __half2float(hp0->x), f1 - __half2float(hp0->y));
        unsigned lo1 = packh2(f2 - __half2float(hp1->x), f3 - __half2float(hp1->y));
        *(unsigned*)(os + t0 + col)          = hi0;
        *(unsigned*)(os + t0 + DMODEL + col) = lo0;
        *(unsigned*)(os + t1 + col)          = hi1;
        *(unsigned*)(os + t1 + DMODEL + col) = lo1;
    }
}

// ---------------------------------------------------------------------------
extern "C" void kernel_launch(void* const* d_in, const int* in_sizes, int n_in,
                              void* d_out, int out_size) {
    const float* x    = (const float*)d_in[0];
    const float* cosp = (const float*)d_in[1];
    const float* sinp = (const float*)d_in[2];
    const float* wq   = (const float*)d_in[3];
    const float* wk   = (const float*)d_in[4];
    const float* wv   = (const float*)d_in[5];
    const float* wo   = (const float*)d_in[6];
    float* out        = (float*)d_out;

    float *pq, *pk, *pv;
    __nv_bfloat16 *pq2, *pk2, *pv2;
    __half *pxs, *pos, *pwqs, *pwks, *pwvs, *pwos;
    cudaGetSymbolAddress((void**)&pq, g_q);
    cudaGetSymbolAddress((void**)&pk, g_k);
    cudaGetSymbolAddress((void**)&pv, g_v);
    cudaGetSymbolAddress((void**)&pq2, g_q2);
    cudaGetSymbolAddress((void**)&pk2, g_k2);
    cudaGetSymbolAddress((void**)&pv2, g_v2);
    cudaGetSymbolAddress((void**)&pxs, g_xs);
    cudaGetSymbolAddress((void**)&pos, g_os);
    cudaGetSymbolAddress((void**)&pwqs, g_wqs);
    cudaGetSymbolAddress((void**)&pwks, g_wks);
    cudaGetSymbolAddress((void**)&pwvs, g_wvs);
    cudaGetSymbolAddress((void**)&pwos, g_wos);

    // fp16x2 splits
    {
        int t1 = TOKENS * DMODEL / 4;
        split_A_kernel<<<(t1 + 255) / 256, 256>>>(x, pxs, TOKENS, DMODEL);
        int t2 = DMODEL * DMODEL / 4;
        split_B_kernel<<<(t2 + 255) / 256, 256>>>(wq, pwqs, DMODEL, DMODEL);
        int t3 = DMODEL * (NKV * HD) / 4;
        split_B_kernel<<<(t3 + 255) / 256, 256>>>(wk, pwks, DMODEL, NKV * HD);
        split_B_kernel<<<(t3 + 255) / 256, 256>>>(wv, pwvs, DMODEL, NKV * HD);
        split_B_kernel<<<(t2 + 255) / 256, 256>>>(wo, pwos, NH * HD, DMODEL);
    }

    // Projections (tensor core fp16x2)
    hgemm_kernel<<<dim3(DMODEL / 128, TOKENS / 128), 256>>>(
        pxs, pwqs, pq, TOKENS, NH * HD, KP2);
    hgemm_kernel<<<dim3((NKV * HD) / 128, TOKENS / 128), 256>>>(
        pxs, pwks, pk, TOKENS, NKV * HD, KP2);
    hgemm_kernel<<<dim3((NKV * HD) / 128, TOKENS / 128), 256>>>(
        pxs, pwvs, pv, TOKENS, NKV * HD, KP2);

    // RoPE + split to bf16 hi/lo
    {
        int total = TOKENS * NH * (HD / 2) + TOKENS * NKV * (HD / 2);
        rope_split_kernel<<<(total + 255) / 256, 256>>>(pq, pk, cosp, sinp, pq2, pk2);
        int tv = TOKENS * NKV * HD;
        vsplit_kernel<<<(tv + 255) / 256, 256>>>(pv, pv2);
    }

    // Attention (tensor core, bf16x3 compensated) -> pre-split fp16 output
    attn_kernel<<<dim3(SEQ / 64, NH, BATCH), 128>>>(pq2, pk2, pv2, pos);

    // Output projection
    hgemm_kernel<<<dim3(DMODEL / 128, TOKENS / 128), 256>>>(
        pos, pwos, out, TOKENS, DMODEL, KP2);
}

// round 6
// speedup vs baseline: 3.9905x; 1.0279x over previous
#include <cuda_runtime.h>
#include <cuda_bf16.h>
#include <cuda_fp16.h>
#include <cstdint>
#include <math.h>

#define BATCH 2
#define SEQ 2048
#define DMODEL 2048
#define NH 32
#define NKV 8
#define HD 64
#define TOKENS (BATCH * SEQ) /* 4096 */
#define KP2 (2 * DMODEL)     /* 4096 expanded-K for fp16x2 */
#define NQKV (NH * HD + 2 * NKV * HD) /* 3072 fused output width */
#define KOFF (NH * HD)                /* 2048 */
#define VOFF (NH * HD + NKV * HD)     /* 2560 */

// ---------------- scratch (device globals; no cudaMalloc allowed) ----------
__device__ float g_qkv[TOKENS * NQKV];              // fused q|k|v projections

__device__ __nv_bfloat16 g_q2[TOKENS * NH * 128];   // roped q  [hi|lo] bf16
__device__ __nv_bfloat16 g_k2[TOKENS * NKV * 128];  // roped k  [hi|lo] bf16
__device__ __nv_bfloat16 g_v2[TOKENS * NKV * 128];  // v        [hi|lo] bf16

__device__ __half g_xs[TOKENS * KP2];               // split(x)  [M, 2K] fp16
__device__ __half g_os[TOKENS * KP2];               // attn out, pre-split fp16
// fused B for QKV gemm: [2K, 3072] row-major, rows K..2K duplicate rows 0..K
__device__ __half g_wqkv[KP2 * NQKV];
__device__ __half g_wos[KP2 * DMODEL];              // [2K, 2048] row-major

// ---------------------------------------------------------------------------
// split_A: [M,K] fp32 -> [M,2K] fp16 = [hi | lo]
// ---------------------------------------------------------------------------
__global__ void split_A_kernel(const float* __restrict__ in,
                               __half* __restrict__ out,
                               int M, int K) {
    int idx = blockIdx.x * blockDim.x + threadIdx.x;
    int total = M * K / 4;
    if (idx >= total) return;
    int m = idx / (K / 4);
    int c = (idx % (K / 4)) * 4;
    float4 v = *(const float4*)(in + (size_t)m * K + c);
    float vv[4] = {v.x, v.y, v.z, v.w};
    __half h[4], l[4];
#pragma unroll
    for (int i = 0; i < 4; i++) {
        h[i] = __float2half_rn(vv[i]);
        l[i] = __float2half_rn(vv[i] - __half2float(h[i]));
    }
    uint2 hp, lp;
    unsigned short* hs = (unsigned short*)&hp;
    unsigned short* ls = (unsigned short*)&lp;
#pragma unroll
    for (int i = 0; i < 4; i++) { hs[i] = *(unsigned short*)&h[i]; ls[i] = *(unsigned short*)&l[i]; }
    size_t base = (size_t)m * (2 * K);
    *(uint2*)(out + base + c)     = hp;
    *(uint2*)(out + base + K + c) = lp;
}

// ---------------------------------------------------------------------------
// split_Bcat: W[K,Nsrc] fp32 -> out rows [0..K) and [K..2K) (hi duplicated),
// into a wider destination of row width Ndst at column offset coff.
// out is row-major [2K, Ndst].
// ---------------------------------------------------------------------------
__global__ void split_Bcat_kernel(const float* __restrict__ in,
                                  __half* __restrict__ out,
                                  int K, int Nsrc, int Ndst, int coff) {
    int idx = blockIdx.x * blockDim.x + threadIdx.x;
    int total = K * Nsrc / 4;
    if (idx >= total) return;
    int r = idx / (Nsrc / 4);
    int c = (idx % (Nsrc / 4)) * 4;
    float4 v = *(const float4*)(in + (size_t)r * Nsrc + c);
    float vv[4] = {v.x, v.y, v.z, v.w};
    __half h[4];
#pragma unroll
    for (int i = 0; i < 4; i++) h[i] = __float2half_rn(vv[i]);
    uint2 hp;
    unsigned short* hs = (unsigned short*)&hp;
#pragma unroll
    for (int i = 0; i < 4; i++) hs[i] = *(unsigned short*)&h[i];
    *(uint2*)(out + (size_t)r * Ndst + coff + c)       = hp;
    *(uint2*)(out + (size_t)(K + r) * Ndst + coff + c) = hp;
}

// ---------------------------------------------------------------------------
// mma / ldmatrix / cp.async helpers
// ---------------------------------------------------------------------------
__device__ __forceinline__ void mma16816(float* c, const unsigned* a,
                                         unsigned b0, unsigned b1) {
    asm volatile(
        "mma.sync.aligned.m16n8k16.row.col.f32.bf16.bf16.f32 "
        "{%0,%1,%2,%3}, {%4,%5,%6,%7}, {%8,%9}, {%0,%1,%2,%3};"
        : "+f"(c[0]), "+f"(c[1]), "+f"(c[2]), "+f"(c[3])
        : "r"(a[0]), "r"(a[1]), "r"(a[2]), "r"(a[3]), "r"(b0), "r"(b1));
}
__device__ __forceinline__ void mma16816h(float* c, const unsigned* a,
                                          unsigned b0, unsigned b1) {
    asm volatile(
        "mma.sync.aligned.m16n8k16.row.col.f32.f16.f16.f32 "
        "{%0,%1,%2,%3}, {%4,%5,%6,%7}, {%8,%9}, {%0,%1,%2,%3};"
        : "+f"(c[0]), "+f"(c[1]), "+f"(c[2]), "+f"(c[3])
        : "r"(a[0]), "r"(a[1]), "r"(a[2]), "r"(a[3]), "r"(b0), "r"(b1));
}
__device__ __forceinline__ void ldmx4(unsigned* r, const void* p) {
    unsigned addr = (unsigned)__cvta_generic_to_shared(p);
    asm volatile("ldmatrix.sync.aligned.m8n8.x4.shared.b16 {%0,%1,%2,%3}, [%4];"
                 : "=r"(r[0]), "=r"(r[1]), "=r"(r[2]), "=r"(r[3]) : "r"(addr));
}
__device__ __forceinline__ void ldmx4t(unsigned* r, const void* p) {
    unsigned addr = (unsigned)__cvta_generic_to_shared(p);
    asm volatile("ldmatrix.sync.aligned.m8n8.x4.trans.shared.b16 {%0,%1,%2,%3}, [%4];"
                 : "=r"(r[0]), "=r"(r[1]), "=r"(r[2]), "=r"(r[3]) : "r"(addr));
}
__device__ __forceinline__ unsigned packbf2(float a, float b) {
    __nv_bfloat162 h = __floats2bfloat162_rn(a, b);
    return *(unsigned*)&h;
}
__device__ __forceinline__ unsigned packh2(float a, float b) {
    __half2 h = __floats2half2_rn(a, b);
    return *(unsigned*)&h;
}
__device__ __forceinline__ void cp16(unsigned s, const void* g) {
    asm volatile("cp.async.cg.shared.global [%0], [%1], 16;\n" :: "r"(s), "l"(g));
}
__device__ __forceinline__ void cp_commit() {
    asm volatile("cp.async.commit_group;\n");
}
__device__ __forceinline__ void cp_wait2() {
    asm volatile("cp.async.wait_group 2;\n");
}

// ---------------------------------------------------------------------------
// fp16 tensor-core GEMM: C[M,N] fp32 = A[M,Kp] f16 @ B[Kp,N] f16 (row-major).
// 128x128 tile, BK=32, 256 threads, warp tile 64x32, 3-stage cp.async.
// ---------------------------------------------------------------------------
#define APAD 40
#define BPAD 136
#define ASTG (128 * APAD)
#define BSTG (32 * BPAD)
#define HG_SMEM (3 * (ASTG + BSTG) * 2) /* 56832 bytes */

__global__ __launch_bounds__(256) void hgemm_kernel(
    const __half* __restrict__ A,
    const __half* __restrict__ B,
    float* __restrict__ C,
    int M, int N, int Kp) {
    extern __shared__ char dsm[];
    __half* As = (__half*)dsm;
    __half* Bs = (__half*)(dsm + 3 * ASTG * 2);

    const int tid  = threadIdx.x;
    const int lane = tid & 31;
    const int wid  = tid >> 5;
    const int wm   = wid >> 2;
    const int wn   = wid & 3;
    const int brow = blockIdx.y * 128;
    const int bcol = blockIdx.x * 128;
    const int NIT  = Kp / 32;

    auto prefetch = [&](int it, int buf) {
        __half* as = As + buf * ASTG;
        __half* bs = Bs + buf * BSTG;
#pragma unroll
        for (int i = 0; i < 2; i++) {
            int c = tid + 256 * i;
            int ar = c >> 2, ac = (c & 3) * 8;
            unsigned sa = (unsigned)__cvta_generic_to_shared(&as[ar * APAD + ac]);
            cp16(sa, A + (size_t)(brow + ar) * Kp + it * 32 + ac);
            int br = c >> 4, bc2 = (c & 15) * 8;
            unsigned sb = (unsigned)__cvta_generic_to_shared(&bs[br * BPAD + bc2]);
            cp16(sb, B + (size_t)(it * 32 + br) * N + bcol + bc2);
        }
    };

    float acc[4][4][4];
#pragma unroll
    for (int i = 0; i < 4; i++)
#pragma unroll
        for (int j = 0; j < 4; j++)
#pragma unroll
            for (int t = 0; t < 4; t++) acc[i][j][t] = 0.0f;

    prefetch(0, 0); cp_commit();
    prefetch(1, 1); cp_commit();
    prefetch(2, 2); cp_commit();

    const int lr = lane & 15;
    const int lc = (lane >> 4) * 8;
    int buf = 0;

    for (int it = 0; it < NIT; it++) {
        cp_wait2();
        __syncthreads();
        const __half* a = As + buf * ASTG;
        const __half* b = Bs + buf * BSTG;

#pragma unroll
        for (int kk = 0; kk < 32; kk += 16) {
            unsigned af[4][4], bf[2][4];
#pragma unroll
            for (int mt = 0; mt < 4; mt++)
                ldmx4(af[mt], &a[(wm * 64 + mt * 16 + lr) * APAD + kk + lc]);
#pragma unroll
            for (int nh = 0; nh < 2; nh++)
                ldmx4t(bf[nh], &b[(kk + lr) * BPAD + wn * 32 + nh * 16 + lc]);
#pragma unroll
            for (int mt = 0; mt < 4; mt++)
#pragma unroll
                for (int nt = 0; nt < 4; nt++)
                    mma16816h(acc[mt][nt], af[mt],
                              bf[nt >> 1][(nt & 1) * 2 + 0],
                              bf[nt >> 1][(nt & 1) * 2 + 1]);
        }
        __syncthreads();
        if (it + 3 < NIT) prefetch(it + 3, buf);
        cp_commit();
        buf = (buf == 2) ? 0 : buf + 1;
    }

#pragma unroll
    for (int mt = 0; mt < 4; mt++) {
        int r0 = brow + wm * 64 + mt * 16 + (lane >> 2);
#pragma unroll
        for (int nt = 0; nt < 4; nt++) {
            int cc = bcol + wn * 32 + nt * 8 + (lane & 3) * 2;
            *(float2*)(C + (size_t)r0 * N + cc) =
                make_float2(acc[mt][nt][0], acc[mt][nt][1]);
            *(float2*)(C + (size_t)(r0 + 8) * N + cc) =
                make_float2(acc[mt][nt][2], acc[mt][nt][3]);
        }
    }
}

// ---------------------------------------------------------------------------
// RoPE + bf16 hi/lo split, reading from fused qkv buffer [tok][3072].
// ---------------------------------------------------------------------------
__global__ void rope_split_kernel(const float* __restrict__ qkv,
                                  const float* __restrict__ cosp,
                                  const float* __restrict__ sinp,
                                  __nv_bfloat16* __restrict__ q2,
                                  __nv_bfloat16* __restrict__ k2) {
    const int HALF = HD / 2;
    const int total_q = TOKENS * NH * HALF;
    const int total   = total_q + TOKENS * NKV * HALF;
    int idx = blockIdx.x * blockDim.x + threadIdx.x;
    if (idx >= total) return;

    const float* src;
    __nv_bfloat16* dst;
    int tok, i;
    float scale;
    if (idx < total_q) {
        i = idx % HALF;
        int t = idx / HALF;
        int head = t % NH;
        tok = t / NH;
        src = qkv + (size_t)tok * NQKV + head * HD;
        dst = q2 + ((size_t)tok * NH + head) * 128;
        scale = 0.125f;
    } else {
        int id2 = idx - total_q;
        i = id2 % HALF;
        int t = id2 / HALF;
        int head = t % NKV;
        tok = t / NKV;
        src = qkv + (size_t)tok * NQKV + KOFF + head * HD;
        dst = k2 + ((size_t)tok * NKV + head) * 128;
        scale = 1.0f;
    }
    int pos = tok & (SEQ - 1);
    float c0 = cosp[pos * HD + i];
    float s0 = sinp[pos * HD + i];
    float c1 = cosp[pos * HD + HALF + i];
    float s1 = sinp[pos * HD + HALF + i];
    float a = src[i];
    float b = src[i + HALF];
    float o0 = (a * c0 - b * s0) * scale;
    float o1 = (b * c1 + a * s1) * scale;
    __nv_bfloat16 h0 = __float2bfloat16_rn(o0);
    __nv_bfloat16 h1 = __float2bfloat16_rn(o1);
    dst[i]              = h0;
    dst[i + HALF]       = h1;
    dst[64 + i]         = __float2bfloat16_rn(o0 - __bfloat162float(h0));
    dst[64 + i + HALF]  = __float2bfloat16_rn(o1 - __bfloat162float(h1));
}

__global__ void vsplit_kernel(const float* __restrict__ qkv,
                              __nv_bfloat16* __restrict__ v2) {
    int idx = blockIdx.x * blockDim.x + threadIdx.x;
    if (idx >= TOKENS * NKV * HD) return;
    int d   = idx % HD;
    int th  = idx / HD;
    int kvh = th % NKV;
    int tok = th / NKV;
    float val = qkv[(size_t)tok * NQKV + VOFF + kvh * HD + d];
    __nv_bfloat16 h = __float2bfloat16_rn(val);
    v2[(size_t)th * 128 + d]      = h;
    v2[(size_t)th * 128 + 64 + d] = __float2bfloat16_rn(val - __bfloat162float(h));
}

// ---------------------------------------------------------------------------
// Tensor-core causal GQA flash attention, bf16x3 compensated (unchanged).
// ---------------------------------------------------------------------------
__global__ __launch_bounds__(128) void attn_kernel(
    const __nv_bfloat16* __restrict__ q2,
    const __nv_bfloat16* __restrict__ k2,
    const __nv_bfloat16* __restrict__ v2,
    __half* __restrict__ os) {
    __shared__ __nv_bfloat16 Ks[64][136];
    __shared__ __nv_bfloat16 Vs[64][136];

    const int qt   = blockIdx.x;
    const int h    = blockIdx.y;
    const int b    = blockIdx.z;
    const int kvh  = h >> 2;
    const int tid  = threadIdx.x;
    const int w    = tid >> 5;
    const int lane = tid & 31;
    const int gid  = lane >> 2;
    const int tig  = lane & 3;

    {
        const __nv_bfloat16* qb = q2 + ((size_t)(b * SEQ + qt * 64) * NH + h) * 128;
        for (int i = tid; i < 64 * 16; i += 128) {
            int r = i >> 4, g = i & 15;
            *(uint4*)&Ks[r][g * 8] = *(const uint4*)(qb + (size_t)r * NH * 128 + g * 8);
        }
    }
    __syncthreads();
    unsigned qf[8][4];
    {
        const int lr = lane & 15, lc = (lane >> 4) * 8;
#pragma unroll
        for (int kc = 0; kc < 8; kc++)
            ldmx4(qf[kc], &Ks[w * 16 + lr][kc * 16 + lc]);
    }

    float O[8][4];
#pragma unroll
    for (int nf = 0; nf < 8; nf++)
#pragma unroll
        for (int t = 0; t < 4; t++) O[nf][t] = 0.0f;
    float m0 = -1e30f, m1 = -1e30f, l0 = 0.0f, l1 = 0.0f;

    const int krow = (lane & 7) + ((lane & 16) >> 1);
    const int kcol = (lane & 8);
    const int vlr = lane & 15, vlc = (lane >> 4) * 8;

    for (int kt = 0; kt <= qt; kt++) {
        __syncthreads();
        {
            const __nv_bfloat16* kb = k2 + ((size_t)(b * SEQ + kt * 64) * NKV + kvh) * 128;
            const __nv_bfloat16* vb = v2 + ((size_t)(b * SEQ + kt * 64) * NKV + kvh) * 128;
            for (int i = tid; i < 64 * 16; i += 128) {
                int r = i >> 4, g = i & 15;
                *(uint4*)&Ks[r][g * 8] = *(const uint4*)(kb + (size_t)r * NKV * 128 + g * 8);
                *(uint4*)&Vs[r][g * 8] = *(const uint4*)(vb + (size_t)r * NKV * 128 + g * 8);
            }
        }
        __syncthreads();

        float S[8][4];
#pragma unroll
        for (int nf = 0; nf < 8; nf++)
#pragma unroll
            for (int t = 0; t < 4; t++) S[nf][t] = 0.0f;

#pragma unroll
        for (int ng = 0; ng < 4; ng++) {
#pragma unroll
            for (int kc = 0; kc < 4; kc++) {
                unsigned kb[4];
                ldmx4(kb, &Ks[ng * 16 + krow][kc * 16 + kcol]);
                mma16816(S[2 * ng],     qf[kc],     kb[0], kb[1]);
                mma16816(S[2 * ng + 1], qf[kc],     kb[2], kb[3]);
                mma16816(S[2 * ng],     qf[kc + 4], kb[0], kb[1]);
                mma16816(S[2 * ng + 1], qf[kc + 4], kb[2], kb[3]);
            }
#pragma unroll
            for (int kc = 0; kc < 4; kc++) {
                unsigned kb[4];
                ldmx4(kb, &Ks[ng * 16 + krow][64 + kc * 16 + kcol]);
                mma16816(S[2 * ng],     qf[kc], kb[0], kb[1]);
                mma16816(S[2 * ng + 1], qf[kc], kb[2], kb[3]);
            }
        }

        if (kt == qt) {
            const int r0 = w * 16 + gid, r1 = r0 + 8;
#pragma unroll
            for (int nf = 0; nf < 8; nf++) {
                int cb = nf * 8 + tig * 2;
                if (cb     > r0) S[nf][0] = -1e30f;
                if (cb + 1 > r0) S[nf][1] = -1e30f;
                if (cb     > r1) S[nf][2] = -1e30f;
                if (cb + 1 > r1) S[nf][3] = -1e30f;
            }
        }

        float mx0 = -1e30f, mx1 = -1e30f;
#pragma unroll
        for (int nf = 0; nf < 8; nf++) {
            mx0 = fmaxf(mx0, fmaxf(S[nf][0], S[nf][1]));
            mx1 = fmaxf(mx1, fmaxf(S[nf][2], S[nf][3]));
        }
        mx0 = fmaxf(mx0, __shfl_xor_sync(0xffffffffu, mx0, 1));
        mx0 = fmaxf(mx0, __shfl_xor_sync(0xffffffffu, mx0, 2));
        mx1 = fmaxf(mx1, __shfl_xor_sync(0xffffffffu, mx1, 1));
        mx1 = fmaxf(mx1, __shfl_xor_sync(0xffffffffu, mx1, 2));
        float mn0 = fmaxf(m0, mx0), mn1 = fmaxf(m1, mx1);
        float corr0 = __expf(m0 - mn0), corr1 = __expf(m1 - mn1);
        float ls0 = 0.0f, ls1 = 0.0f;
#pragma unroll
        for (int nf = 0; nf < 8; nf++) {
            S[nf][0] = __expf(S[nf][0] - mn0);
            S[nf][1] = __expf(S[nf][1] - mn0);
            S[nf][2] = __expf(S[nf][2] - mn1);
            S[nf][3] = __expf(S[nf][3] - mn1);
            ls0 += S[nf][0] + S[nf][1];
            ls1 += S[nf][2] + S[nf][3];
        }
        ls0 += __shfl_xor_sync(0xffffffffu, ls0, 1);
        ls0 += __shfl_xor_sync(0xffffffffu, ls0, 2);
        ls1 += __shfl_xor_sync(0xffffffffu, ls1, 1);
        ls1 += __shfl_xor_sync(0xffffffffu, ls1, 2);
        l0 = l0 * corr0 + ls0;
        l1 = l1 * corr1 + ls1;
        m0 = mn0; m1 = mn1;
#pragma unroll
        for (int nf = 0; nf < 8; nf++) {
            O[nf][0] *= corr0; O[nf][1] *= corr0;
            O[nf][2] *= corr1; O[nf][3] *= corr1;
        }

        unsigned pha[4][4], pla[4][4];
#pragma unroll
        for (int kc = 0; kc < 4; kc++) {
            float p00 = S[2 * kc][0],     p01 = S[2 * kc][1];
            float p10 = S[2 * kc][2],     p11 = S[2 * kc][3];
            float p20 = S[2 * kc + 1][0], p21 = S[2 * kc + 1][1];
            float p30 = S[2 * kc + 1][2], p31 = S[2 * kc + 1][3];
            pha[kc][0] = packbf2(p00, p01);
            pha[kc][1] = packbf2(p10, p11);
            pha[kc][2] = packbf2(p20, p21);
            pha[kc][3] = packbf2(p30, p31);
            __nv_bfloat162* hp;
            hp = (__nv_bfloat162*)&pha[kc][0];
            pla[kc][0] = packbf2(p00 - __bfloat162float(hp->x), p01 - __bfloat162float(hp->y));
            hp = (__nv_bfloat162*)&pha[kc][1];
            pla[kc][1] = packbf2(p10 - __bfloat162float(hp->x), p11 - __bfloat162float(hp->y));
            hp = (__nv_bfloat162*)&pha[kc][2];
            pla[kc][2] = packbf2(p20 - __bfloat162float(hp->x), p21 - __bfloat162float(hp->y));
            hp = (__nv_bfloat162*)&pha[kc][3];
            pla[kc][3] = packbf2(p30 - __bfloat162float(hp->x), p31 - __bfloat162float(hp->y));
        }

#pragma unroll
        for (int kc = 0; kc < 4; kc++) {
#pragma unroll
            for (int ns = 0; ns < 4; ns++) {
                unsigned vb[4];
                ldmx4t(vb, &Vs[kc * 16 + vlr][ns * 16 + vlc]);
                mma16816(O[2 * ns],     pha[kc], vb[0], vb[1]);
                mma16816(O[2 * ns + 1], pha[kc], vb[2], vb[3]);
                mma16816(O[2 * ns],     pla[kc], vb[0], vb[1]);
                mma16816(O[2 * ns + 1], pla[kc], vb[2], vb[3]);
                ldmx4t(vb, &Vs[kc * 16 + vlr][64 + ns * 16 + vlc]);
                mma16816(O[2 * ns],     pha[kc], vb[0], vb[1]);
                mma16816(O[2 * ns + 1], pha[kc], vb[2], vb[3]);
            }
        }
    }

    float inv0 = 1.0f / l0, inv1 = 1.0f / l1;
    size_t t0 = (size_t)(b * SEQ + qt * 64 + w * 16 + gid) * KP2;
    size_t t1 = t0 + (size_t)8 * KP2;
#pragma unroll
    for (int nf = 0; nf < 8; nf++) {
        int col = h * 64 + nf * 8 + tig * 2;
        float f0 = O[nf][0] * inv0, f1 = O[nf][1] * inv0;
        float f2 = O[nf][2] * inv1, f3 = O[nf][3] * inv1;
        unsigned hi0 = packh2(f0, f1);
        unsigned hi1 = packh2(f2, f3);
        __half2* hp0 = (__half2*)&hi0;
        __half2* hp1 = (__half2*)&hi1;
        unsigned lo0 = packh2(f0 - __half2float(hp0->x), f1 - __half2float(hp0->y));
        unsigned lo1 = packh2(f2 - __half2float(hp1->x), f3 - __half2float(hp1->y));
        *(unsigned*)(os + t0 + col)          = hi0;
        *(unsigned*)(os + t0 + DMODEL + col) = lo0;
        *(unsigned*)(os + t1 + col)          = hi1;
        *(unsigned*)(os + t1 + DMODEL + col) = lo1;
    }
}

// ---------------------------------------------------------------------------
extern "C" void kernel_launch(void* const* d_in, const int* in_sizes, int n_in,
                              void* d_out, int out_size) {
    const float* x    = (const float*)d_in[0];
    const float* cosp = (const float*)d_in[1];
    const float* sinp = (const float*)d_in[2];
    const float* wq   = (const float*)d_in[3];
    const float* wk   = (const float*)d_in[4];
    const float* wv   = (const float*)d_in[5];
    const float* wo   = (const float*)d_in[6];
    float* out        = (float*)d_out;

    float* pqkv;
    __nv_bfloat16 *pq2, *pk2, *pv2;
    __half *pxs, *pos, *pwqkv, *pwos;
    cudaGetSymbolAddress((void**)&pqkv, g_qkv);
    cudaGetSymbolAddress((void**)&pq2, g_q2);
    cudaGetSymbolAddress((void**)&pk2, g_k2);
    cudaGetSymbolAddress((void**)&pv2, g_v2);
    cudaGetSymbolAddress((void**)&pxs, g_xs);
    cudaGetSymbolAddress((void**)&pos, g_os);
    cudaGetSymbolAddress((void**)&pwqkv, g_wqkv);
    cudaGetSymbolAddress((void**)&pwos, g_wos);

    cudaFuncSetAttribute(hgemm_kernel,
                         cudaFuncAttributeMaxDynamicSharedMemorySize, HG_SMEM);

    // fp16 splits: x -> [M,2K]; fused B -> [2K,3072]; wo -> [2K,2048]
    {
        int t1 = TOKENS * DMODEL / 4;
        split_A_kernel<<<(t1 + 255) / 256, 256>>>(x, pxs, TOKENS, DMODEL);
        int tq = DMODEL * DMODEL / 4;
        split_Bcat_kernel<<<(tq + 255) / 256, 256>>>(wq, pwqkv, DMODEL, DMODEL, NQKV, 0);
        int tk = DMODEL * (NKV * HD) / 4;
        split_Bcat_kernel<<<(tk + 255) / 256, 256>>>(wk, pwqkv, DMODEL, NKV * HD, NQKV, KOFF);
        split_Bcat_kernel<<<(tk + 255) / 256, 256>>>(wv, pwqkv, DMODEL, NKV * HD, NQKV, VOFF);
        split_Bcat_kernel<<<(tq + 255) / 256, 256>>>(wo, pwos, NH * HD, DMODEL, DMODEL, 0);
    }

    // Fused QKV projection: [4096,4096] @ [4096,3072]
    hgemm_kernel<<<dim3(NQKV / 128, TOKENS / 128), 256, HG_SMEM>>>(
        pxs, pwqkv, pqkv, TOKENS, NQKV, KP2);

    // RoPE + split to bf16 hi/lo (reads fused buffer)
    {
        int total = TOKENS * NH * (HD / 2) + TOKENS * NKV * (HD / 2);
        rope_split_kernel<<<(total + 255) / 256, 256>>>(pqkv, cosp, sinp, pq2, pk2);
        int tv = TOKENS * NKV * HD;
        vsplit_kernel<<<(tv + 255) / 256, 256>>>(pqkv, pv2);
    }

    // Attention -> pre-split fp16 output
    attn_kernel<<<dim3(SEQ / 64, NH, BATCH), 128>>>(pq2, pk2, pv2, pos);

    // Output projection
    hgemm_kernel<<<dim3(DMODEL / 128, TOKENS / 128), 256, HG_SMEM>>>(
        pos, pwos, out, TOKENS, DMODEL, KP2);
}